// round 5
// baseline (speedup 1.0000x reference)
#include <cuda_runtime.h>
#include <cuda_bf16.h>
#include <math.h>
#include <stdint.h>

// Problem constants
#define BB   2
#define TT   2048
#define CC   1024
#define HH   16
#define DD   64
#define MTOT (BB*TT)          // 4096
#define QKVN (3*CC)           // 3072

// ---------------- scratch (device globals; no allocs allowed) ----------------
__device__ float g_qkv[(size_t)MTOT * QKVN];      // 4096 x 3072
__device__ float g_q[(size_t)BB*HH*TT*DD];        // [B*H, T, D]
__device__ float g_k[(size_t)BB*HH*TT*DD];
__device__ float g_v[(size_t)BB*HH*TT*DD];
__device__ float g_att[(size_t)MTOT * CC];        // [B,T,C] attention output

// bf16 split operands
__device__ __nv_bfloat16 g_xh[(size_t)MTOT * CC];       // x hi
__device__ __nv_bfloat16 g_xl[(size_t)MTOT * CC];       // x lo
__device__ __nv_bfloat16 g_wqkvTh[(size_t)QKVN * CC];   // Wqkv^T hi  [N,K]
__device__ __nv_bfloat16 g_wqkvTl[(size_t)QKVN * CC];
__device__ __nv_bfloat16 g_ath[(size_t)MTOT * CC];      // att hi
__device__ __nv_bfloat16 g_atl[(size_t)MTOT * CC];
__device__ __nv_bfloat16 g_woTh[(size_t)CC * CC];       // Wo^T hi    [N,K]
__device__ __nv_bfloat16 g_woTl[(size_t)CC * CC];

// ---------------- helpers -----------------------------------------------------
__device__ __forceinline__ uint32_t smem_u32(const void* p) {
    uint32_t a;
    asm("{ .reg .u64 t; cvta.to.shared.u64 t, %1; cvt.u32.u64 %0, t; }"
        : "=r"(a) : "l"(p));
    return a;
}
__device__ __forceinline__ uint32_t sw128(uint32_t b) { return b ^ ((b >> 3) & 0x70); }

__device__ __forceinline__ void ldsm4(uint32_t* r, uint32_t addr) {
    asm volatile("ldmatrix.sync.aligned.m8n8.x4.shared.b16 {%0,%1,%2,%3}, [%4];"
                 : "=r"(r[0]), "=r"(r[1]), "=r"(r[2]), "=r"(r[3]) : "r"(addr));
}
__device__ __forceinline__ void mma_bf16(float* c, const uint32_t* a, const uint32_t* b) {
    asm volatile(
        "mma.sync.aligned.m16n8k16.row.col.f32.bf16.bf16.f32 "
        "{%0,%1,%2,%3}, {%4,%5,%6,%7}, {%8,%9}, {%0,%1,%2,%3};"
        : "+f"(c[0]), "+f"(c[1]), "+f"(c[2]), "+f"(c[3])
        : "r"(a[0]), "r"(a[1]), "r"(a[2]), "r"(a[3]), "r"(b[0]), "r"(b[1]));
}

// ---------------- HMMA split-bf16 GEMM: C[M,Ntot] = A@B^T (+bias) ------------
// A(hi/lo): [M,K] bf16 row-major.  B(hi/lo): [Ntot,K] bf16 row-major.
// CTA: 128x128 tile, Ktile=64, 8 warps (2x4), warp tile 64x32.
#define MM_THREADS 256
#define KTB 64
#define TILE_BYTES 16384                  // 128 rows * 128B
#define SM_AH 0
#define SM_AL 16384
#define SM_BH 32768
#define SM_BL 49152
#define SM_TOTAL 65536

__global__ __launch_bounds__(MM_THREADS, 2)
void mm_bf16_kernel(const __nv_bfloat16* __restrict__ Ah,
                    const __nv_bfloat16* __restrict__ Al,
                    const __nv_bfloat16* __restrict__ Bh,
                    const __nv_bfloat16* __restrict__ Bl,
                    const float* __restrict__ bias,
                    float* __restrict__ C,
                    int Ntot, int K)
{
    extern __shared__ __align__(1024) char smem[];
    const uint32_t sb = smem_u32(smem);
    const int tid  = threadIdx.x;
    const int wid  = tid >> 5;
    const int lane = tid & 31;
    const int m0 = blockIdx.y * 128;
    const int n0 = blockIdx.x * 128;
    const int wm = wid >> 2;              // 0..1  (64 rows each)
    const int wn = wid & 3;               // 0..3  (32 cols each)

    // ldmatrix per-lane source mapping
    const int a_row = (lane & 7) | (((lane >> 3) & 1) << 3);   // 0..15
    const int a_kb  = (lane >> 4) * 16;                         // byte k-half
    const int b_row = (lane & 7) | ((lane >> 4) << 3);          // n offset 0..15
    const int b_kb  = ((lane >> 3) & 1) * 16;

    float acc[4][4][4] = {};

    const int NT = K / KTB;               // 16

    for (int t = 0; t < NT; t++) {
        const int k0 = t * KTB;
        // ---- fill 4 SMEM tiles (Ah, Al, Bh, Bl), SW128-swizzled ----
#pragma unroll
        for (int i = 0; i < 4; i++) {
            const int chunk = tid + i * MM_THREADS;    // 0..1023
            const int r = chunk >> 3;
            const int c = chunk & 7;
            const uint32_t so = sw128((uint32_t)(r * 128 + c * 16));
            const size_t aoff = (size_t)(m0 + r) * K + k0 + c * 8;
            const size_t boff = (size_t)(n0 + r) * K + k0 + c * 8;
            *(uint4*)(smem + SM_AH + so) = *(const uint4*)(Ah + aoff);
            *(uint4*)(smem + SM_AL + so) = *(const uint4*)(Al + aoff);
            *(uint4*)(smem + SM_BH + so) = *(const uint4*)(Bh + boff);
            *(uint4*)(smem + SM_BL + so) = *(const uint4*)(Bl + boff);
        }
        __syncthreads();

#pragma unroll
        for (int k16 = 0; k16 < 4; k16++) {
            const int kb2 = k16 * 32;     // byte offset of this k16 step

            uint32_t bh[4][2], bl[4][2], af[4][4];
            // B fragments: 2 x ldmatrix.x4 covers 4 n8 groups
#pragma unroll
            for (int g = 0; g < 2; g++) {
                const uint32_t off =
                    sw128((uint32_t)((wn * 32 + g * 16 + b_row) * 128 + kb2 + b_kb));
                uint32_t r[4];
                ldsm4(r, sb + SM_BH + off);
                bh[g*2][0] = r[0]; bh[g*2][1] = r[1];
                bh[g*2+1][0] = r[2]; bh[g*2+1][1] = r[3];
                ldsm4(r, sb + SM_BL + off);
                bl[g*2][0] = r[0]; bl[g*2][1] = r[1];
                bl[g*2+1][0] = r[2]; bl[g*2+1][1] = r[3];
            }
            // A-hi fragments, then hh + hl products
#pragma unroll
            for (int mi = 0; mi < 4; mi++) {
                const uint32_t off =
                    sw128((uint32_t)((wm * 64 + mi * 16 + a_row) * 128 + kb2 + a_kb));
                ldsm4(af[mi], sb + SM_AH + off);
            }
#pragma unroll
            for (int mi = 0; mi < 4; mi++)
#pragma unroll
                for (int ni = 0; ni < 4; ni++) {
                    mma_bf16(acc[mi][ni], af[mi], bh[ni]);
                    mma_bf16(acc[mi][ni], af[mi], bl[ni]);
                }
            // A-lo fragments, lh product
#pragma unroll
            for (int mi = 0; mi < 4; mi++) {
                const uint32_t off =
                    sw128((uint32_t)((wm * 64 + mi * 16 + a_row) * 128 + kb2 + a_kb));
                ldsm4(af[mi], sb + SM_AL + off);
            }
#pragma unroll
            for (int mi = 0; mi < 4; mi++)
#pragma unroll
                for (int ni = 0; ni < 4; ni++)
                    mma_bf16(acc[mi][ni], af[mi], bh[ni]);
        }
        __syncthreads();
    }

    // ---- epilogue: fragment -> global fp32 (+bias) ----
    const int g   = lane >> 2;
    const int tig = lane & 3;
#pragma unroll
    for (int mi = 0; mi < 4; mi++) {
#pragma unroll
        for (int ni = 0; ni < 4; ni++) {
            const int row = m0 + wm * 64 + mi * 16 + g;
            const int col = n0 + wn * 32 + ni * 8 + tig * 2;
            float2 v0, v1;
            v0.x = acc[mi][ni][0]; v0.y = acc[mi][ni][1];
            v1.x = acc[mi][ni][2]; v1.y = acc[mi][ni][3];
            if (bias) {
                const float b0 = bias[col], b1 = bias[col + 1];
                v0.x += b0; v0.y += b1;
                v1.x += b0; v1.y += b1;
            }
            *(float2*)(C + (size_t)row * Ntot + col)       = v0;
            *(float2*)(C + (size_t)(row + 8) * Ntot + col) = v1;
        }
    }
}

// ---------------- fp32 -> bf16 hi/lo split (same layout) ---------------------
__global__ void split_kernel(const float* __restrict__ in,
                             __nv_bfloat16* __restrict__ hi,
                             __nv_bfloat16* __restrict__ lo, int n4)
{
    int i = blockIdx.x * blockDim.x + threadIdx.x;
    if (i >= n4) return;
    float4 v = ((const float4*)in)[i];
    __nv_bfloat16 h0 = __float2bfloat16(v.x);
    __nv_bfloat16 h1 = __float2bfloat16(v.y);
    __nv_bfloat16 h2 = __float2bfloat16(v.z);
    __nv_bfloat16 h3 = __float2bfloat16(v.w);
    __nv_bfloat162 H0, H1, L0, L1;
    H0.x = h0; H0.y = h1; H1.x = h2; H1.y = h3;
    L0.x = __float2bfloat16(v.x - __bfloat162float(h0));
    L0.y = __float2bfloat16(v.y - __bfloat162float(h1));
    L1.x = __float2bfloat16(v.z - __bfloat162float(h2));
    L1.y = __float2bfloat16(v.w - __bfloat162float(h3));
    ((__nv_bfloat162*)hi)[i * 2 + 0] = H0;
    ((__nv_bfloat162*)hi)[i * 2 + 1] = H1;
    ((__nv_bfloat162*)lo)[i * 2 + 0] = L0;
    ((__nv_bfloat162*)lo)[i * 2 + 1] = L1;
}

// ---------------- fp32 [K,N] -> bf16 hi/lo transposed [N,K] ------------------
__global__ void transpose_split_kernel(const float* __restrict__ W,
                                       __nv_bfloat16* __restrict__ Th,
                                       __nv_bfloat16* __restrict__ Tl,
                                       int K, int N)
{
    __shared__ float tile[32][33];
    const int n0 = blockIdx.x * 32;
    const int k0 = blockIdx.y * 32;
    const int tx = threadIdx.x;
    const int ty = threadIdx.y;           // 0..7
#pragma unroll
    for (int i = 0; i < 4; i++) {
        int k = k0 + ty + i * 8;
        tile[ty + i * 8][tx] = W[(size_t)k * N + n0 + tx];
    }
    __syncthreads();
#pragma unroll
    for (int i = 0; i < 4; i++) {
        int n = n0 + ty + i * 8;
        float v = tile[tx][ty + i * 8];
        __nv_bfloat16 h = __float2bfloat16(v);
        Th[(size_t)n * K + k0 + tx] = h;
        Tl[(size_t)n * K + k0 + tx] = __float2bfloat16(v - __bfloat162float(h));
    }
}

// ---------------- RoPE + scatter to [B*H, T, D] ------------------------------
__global__ void rope_scatter_kernel()
{
    int idx = blockIdx.x * blockDim.x + threadIdx.x;
    const int TOT = MTOT * 3 * HH * (DD / 2);
    if (idx >= TOT) return;

    int row = idx / 1536;            // b*T + t
    int c0  = idx % 1536;
    int sel = c0 / 512;              // 0=q 1=k 2=v
    int h   = (c0 % 512) / 32;
    int p   = c0 % 32;               // pair index (d = 2p, 2p+1)
    int t   = row % TT;
    int b   = row / TT;

    size_t src = (size_t)row * QKVN + sel * CC + h * DD + 2 * p;
    float x0 = g_qkv[src];
    float x1 = g_qkv[src + 1];

    float* dst = (sel == 0) ? g_q : (sel == 1) ? g_k : g_v;
    size_t o = ((size_t)(b * HH + h) * TT + t) * DD + 2 * p;

    if (sel < 2) {
        const float LN1E4_OVER_32 = 0.28782313662425572f;
        float inv_freq = __expf(-(float)p * LN1E4_OVER_32);
        float ang = (float)t * inv_freq;
        float s, c;
        sincosf(ang, &s, &c);
        dst[o]     = x0 * c - x1 * s;
        dst[o + 1] = x1 * c + x0 * s;
    } else {
        dst[o]     = x0;
        dst[o + 1] = x1;
    }
}

// ---------------- flash attention (fp32, causal, online softmax) --------------
#define AT_THREADS 256
#define AT_BQ 128        // queries per CTA
#define AT_BKT 64        // keys per SMEM tile
#define AT_CH 16         // keys per softmax chunk

__global__ __launch_bounds__(AT_THREADS)
void attn_kernel()
{
    __shared__ float Ks[AT_BKT][DD];
    __shared__ float Vs[AT_BKT][DD];

    const int bh   = blockIdx.y;             // b*16 + h
    const int q0   = blockIdx.x * AT_BQ;
    const int tid  = threadIdx.x;
    const int warp = tid >> 5;
    const int lane = tid & 31;
    const int qloc = lane & 15;              // query within warp
    const int dh   = lane >> 4;              // dim half: 0 or 1
    const int qi   = q0 + warp * 16 + qloc;
    const int dbase = dh * 32;

    const float* Qb = g_q + ((size_t)bh * TT + qi) * DD + dbase;
    const float* Kb = g_k + (size_t)bh * TT * DD;
    const float* Vb = g_v + (size_t)bh * TT * DD;

    float q[32];
#pragma unroll
    for (int d = 0; d < 32; d += 4) {
        float4 v = *(const float4*)(Qb + d);
        q[d + 0] = v.x * 0.125f;
        q[d + 1] = v.y * 0.125f;
        q[d + 2] = v.z * 0.125f;
        q[d + 3] = v.w * 0.125f;
    }

    float m = -INFINITY, l = 0.0f;
    float acc[32] = {};

    const int wqmax = q0 + warp * 16 + 15;   // warp's last query (uniform)
    const int kend  = q0 + AT_BQ;

    for (int j0 = 0; j0 < kend; j0 += AT_BKT) {
#pragma unroll
        for (int i = 0; i < (AT_BKT * DD / 4) / AT_THREADS; i++) {   // 4 iters
            int e = tid + i * AT_THREADS;
            ((float4*)&Ks[0][0])[e] = ((const float4*)(Kb + (size_t)j0 * DD))[e];
            ((float4*)&Vs[0][0])[e] = ((const float4*)(Vb + (size_t)j0 * DD))[e];
        }
        __syncthreads();

        for (int c0 = 0; c0 < AT_BKT; c0 += AT_CH) {
            const int kbase = j0 + c0;
            if (kbase > wqmax) break;        // warp-uniform

            float s[AT_CH];
#pragma unroll
            for (int j = 0; j < AT_CH; j++) {
                const float* kr = &Ks[c0 + j][dbase];
                float ps0 = 0.f, ps1 = 0.f, ps2 = 0.f, ps3 = 0.f;
#pragma unroll
                for (int d = 0; d < 32; d += 16) {
                    float4 a = *(const float4*)(kr + d + 0);
                    float4 b = *(const float4*)(kr + d + 4);
                    float4 c = *(const float4*)(kr + d + 8);
                    float4 e = *(const float4*)(kr + d + 12);
                    ps0 += q[d + 0]*a.x + q[d + 1]*a.y + q[d + 2]*a.z + q[d + 3]*a.w;
                    ps1 += q[d + 4]*b.x + q[d + 5]*b.y + q[d + 6]*b.z + q[d + 7]*b.w;
                    ps2 += q[d + 8]*c.x + q[d + 9]*c.y + q[d +10]*c.z + q[d +11]*c.w;
                    ps3 += q[d +12]*e.x + q[d +13]*e.y + q[d +14]*e.z + q[d +15]*e.w;
                }
                float part = (ps0 + ps1) + (ps2 + ps3);
                float full = part + __shfl_xor_sync(0xffffffffu, part, 16);
                s[j] = (kbase + j > qi) ? -INFINITY : full;
            }

            float mt = m;
#pragma unroll
            for (int j = 0; j < AT_CH; j++) mt = fmaxf(mt, s[j]);

            if (mt > -INFINITY) {
                float r = __expf(m - mt);
                l *= r;
#pragma unroll
                for (int d = 0; d < 32; d++) acc[d] *= r;
                m = mt;

#pragma unroll
                for (int j = 0; j < AT_CH; j++) {
                    float p = __expf(s[j] - m);
                    l += p;
                    const float* vr = &Vs[c0 + j][dbase];
#pragma unroll
                    for (int d = 0; d < 32; d += 4) {
                        float4 vv = *(const float4*)(vr + d);
                        acc[d + 0] += p * vv.x;
                        acc[d + 1] += p * vv.y;
                        acc[d + 2] += p * vv.z;
                        acc[d + 3] += p * vv.w;
                    }
                }
            }
        }
        __syncthreads();
    }

    const int b = bh >> 4;
    const int h = bh & 15;
    const float inv = 1.0f / l;
    float* op = g_att + ((size_t)(b * TT + qi)) * CC + h * DD + dbase;
#pragma unroll
    for (int d = 0; d < 32; d += 4) {
        float4 v;
        v.x = acc[d + 0] * inv;
        v.y = acc[d + 1] * inv;
        v.z = acc[d + 2] * inv;
        v.w = acc[d + 3] * inv;
        *(float4*)(op + d) = v;
    }
}

// ---------------- launch ------------------------------------------------------
extern "C" void kernel_launch(void* const* d_in, const int* in_sizes, int n_in,
                              void* d_out, int out_size)
{
    const float* x    = (const float*)d_in[0];
    const float* Wqkv = (const float*)d_in[1];
    const float* Wo   = (const float*)d_in[2];
    const float* bo   = (const float*)d_in[3];
    float* out = (float*)d_out;

    (void)in_sizes; (void)n_in; (void)out_size;

    static int smem_set = 0;
    if (!smem_set) {
        cudaFuncSetAttribute(mm_bf16_kernel,
                             cudaFuncAttributeMaxDynamicSharedMemorySize, SM_TOTAL);
        smem_set = 1;
    }

    __nv_bfloat16 *xh, *xl, *wqh, *wql, *ath, *atl, *woh, *wol;
    cudaGetSymbolAddress((void**)&xh,  g_xh);
    cudaGetSymbolAddress((void**)&xl,  g_xl);
    cudaGetSymbolAddress((void**)&wqh, g_wqkvTh);
    cudaGetSymbolAddress((void**)&wql, g_wqkvTl);
    cudaGetSymbolAddress((void**)&ath, g_ath);
    cudaGetSymbolAddress((void**)&atl, g_atl);
    cudaGetSymbolAddress((void**)&woh, g_woTh);
    cudaGetSymbolAddress((void**)&wol, g_woTl);
    float *qkvp, *attp;
    cudaGetSymbolAddress((void**)&qkvp, g_qkv);
    cudaGetSymbolAddress((void**)&attp, g_att);

    // 1) split x to bf16 hi/lo
    {
        int n4 = MTOT * CC / 4;
        split_kernel<<<(n4 + 255) / 256, 256>>>(x, xh, xl, n4);
    }
    // 2) transpose+split Wqkv -> [3072,1024]
    {
        dim3 grid(QKVN / 32, CC / 32);
        transpose_split_kernel<<<grid, dim3(32, 8)>>>(Wqkv, wqh, wql, CC, QKVN);
    }
    // 3) QKV GEMM (HMMA): [4096,1024] x [3072,1024]^T
    {
        dim3 grid(QKVN / 128, MTOT / 128);   // (24, 32)
        mm_bf16_kernel<<<grid, MM_THREADS, SM_TOTAL>>>(
            xh, xl, wqh, wql, nullptr, qkvp, QKVN, CC);
    }
    // 4) RoPE + scatter
    {
        int tot = MTOT * 3 * HH * (DD / 2);
        rope_scatter_kernel<<<(tot + 255) / 256, 256>>>();
    }
    // 5) causal flash attention
    {
        dim3 grid(TT / AT_BQ, BB * HH);
        attn_kernel<<<grid, AT_THREADS>>>();
    }
    // 6) split attention output
    {
        int n4 = MTOT * CC / 4;
        split_kernel<<<(n4 + 255) / 256, 256>>>(attp, ath, atl, n4);
    }
    // 7) transpose+split Wo -> [1024,1024]
    {
        dim3 grid(CC / 32, CC / 32);
        transpose_split_kernel<<<grid, dim3(32, 8)>>>(Wo, woh, wol, CC, CC);
    }
    // 8) output projection (HMMA) + bias
    {
        dim3 grid(CC / 128, MTOT / 128);     // (8, 32)
        mm_bf16_kernel<<<grid, MM_THREADS, SM_TOTAL>>>(
            ath, atl, woh, wol, bo, out, CC, CC);
    }
}

// round 6
// speedup vs baseline: 1.6763x; 1.6763x over previous
#include <cuda_runtime.h>
#include <cuda_bf16.h>
#include <math.h>
#include <stdint.h>

// Problem constants
#define BB   2
#define TT   2048
#define CC   1024
#define HH   16
#define DD   64
#define MTOT (BB*TT)          // 4096
#define QKVN (3*CC)           // 3072

// ---------------- scratch (device globals; no allocs allowed) ----------------
__device__ float g_qkv[(size_t)MTOT * QKVN];      // 4096 x 3072
__device__ float g_q[(size_t)BB*HH*TT*DD];        // [B*H, T, D]
__device__ float g_k[(size_t)BB*HH*TT*DD];
__device__ float g_v[(size_t)BB*HH*TT*DD];

// bf16 split operands
__device__ __nv_bfloat16 g_xh[(size_t)MTOT * CC];       // x hi
__device__ __nv_bfloat16 g_xl[(size_t)MTOT * CC];       // x lo
__device__ __nv_bfloat16 g_wqkvTh[(size_t)QKVN * CC];   // Wqkv^T hi  [N,K]
__device__ __nv_bfloat16 g_wqkvTl[(size_t)QKVN * CC];
__device__ __nv_bfloat16 g_ath[(size_t)MTOT * CC];      // attention out hi
__device__ __nv_bfloat16 g_atl[(size_t)MTOT * CC];      // attention out lo
__device__ __nv_bfloat16 g_woTh[(size_t)CC * CC];       // Wo^T hi    [N,K]
__device__ __nv_bfloat16 g_woTl[(size_t)CC * CC];

// ---------------- helpers -----------------------------------------------------
__device__ __forceinline__ uint32_t smem_u32(const void* p) {
    uint32_t a;
    asm("{ .reg .u64 t; cvta.to.shared.u64 t, %1; cvt.u32.u64 %0, t; }"
        : "=r"(a) : "l"(p));
    return a;
}
__device__ __forceinline__ uint32_t sw128(uint32_t b) { return b ^ ((b >> 3) & 0x70); }

__device__ __forceinline__ void ldsm4(uint32_t* r, uint32_t addr) {
    asm volatile("ldmatrix.sync.aligned.m8n8.x4.shared.b16 {%0,%1,%2,%3}, [%4];"
                 : "=r"(r[0]), "=r"(r[1]), "=r"(r[2]), "=r"(r[3]) : "r"(addr));
}
__device__ __forceinline__ void mma_bf16(float* c, const uint32_t* a, const uint32_t* b) {
    asm volatile(
        "mma.sync.aligned.m16n8k16.row.col.f32.bf16.bf16.f32 "
        "{%0,%1,%2,%3}, {%4,%5,%6,%7}, {%8,%9}, {%0,%1,%2,%3};"
        : "+f"(c[0]), "+f"(c[1]), "+f"(c[2]), "+f"(c[3])
        : "r"(a[0]), "r"(a[1]), "r"(a[2]), "r"(a[3]), "r"(b[0]), "r"(b[1]));
}
__device__ __forceinline__ void cpasync16(uint32_t dst, const void* src) {
    asm volatile("cp.async.cg.shared.global [%0], [%1], 16;"
                 :: "r"(dst), "l"(src) : "memory");
}

// ---------------- HMMA split-bf16 GEMM: C[M,Ntot] = A@B^T (+bias) ------------
// A(hi/lo): [M,K] bf16 row-major.  B(hi/lo): [Ntot,K] bf16 row-major.
// CTA: 128x128 tile, Ktile=64, 8 warps (2x4), warp tile 64x32.
// cp.async double-buffered (2 x 64KB smem), 1 CTA/SM, full register budget.
#define MM_THREADS 256
#define KTB 64
#define SM_AH 0
#define SM_AL 16384
#define SM_BH 32768
#define SM_BL 49152
#define BUF_BYTES 65536
#define SM_TOTAL (2*BUF_BYTES)            // 131072

__global__ __launch_bounds__(MM_THREADS)
void mm_bf16_kernel(const __nv_bfloat16* __restrict__ Ah,
                    const __nv_bfloat16* __restrict__ Al,
                    const __nv_bfloat16* __restrict__ Bh,
                    const __nv_bfloat16* __restrict__ Bl,
                    const float* __restrict__ bias,
                    float* __restrict__ C,
                    int Ntot, int K)
{
    extern __shared__ __align__(1024) char smem[];
    const uint32_t sb = smem_u32(smem);
    const int tid  = threadIdx.x;
    const int wid  = tid >> 5;
    const int lane = tid & 31;
    const int m0 = blockIdx.y * 128;
    const int n0 = blockIdx.x * 128;
    const int wm = wid >> 2;              // 0..1  (64 rows each)
    const int wn = wid & 3;               // 0..3  (32 cols each)

    // ldmatrix per-lane source mapping
    const int a_row = (lane & 7) | (((lane >> 3) & 1) << 3);   // 0..15
    const int a_kb  = (lane >> 4) * 16;                         // byte k-half
    const int b_row = (lane & 7) | ((lane >> 4) << 3);          // n offset 0..15
    const int b_kb  = ((lane >> 3) & 1) * 16;

    // per-thread cp.async source/dst precompute
    const int cr = tid >> 3;              // row 0..31 handled (4 passes -> 128)
    const int cc = tid & 7;               // 16B chunk in row
    const uint32_t so_base = (uint32_t)(cr * 128 + cc * 16);

    float acc[4][4][4] = {};

    const int NT = K / KTB;               // 16

    auto issue_tile = [&](int t) {
        const int k0 = t * KTB;
        const uint32_t bb = (uint32_t)(t & 1) * BUF_BYTES;
#pragma unroll
        for (int i = 0; i < 4; i++) {
            const int r = cr + i * 32;
            const uint32_t so = sw128(so_base + (uint32_t)i * 32 * 128);
            const size_t aoff = (size_t)(m0 + r) * K + k0 + cc * 8;
            const size_t boff = (size_t)(n0 + r) * K + k0 + cc * 8;
            cpasync16(sb + bb + SM_AH + so, Ah + aoff);
            cpasync16(sb + bb + SM_AL + so, Al + aoff);
            cpasync16(sb + bb + SM_BH + so, Bh + boff);
            cpasync16(sb + bb + SM_BL + so, Bl + boff);
        }
        asm volatile("cp.async.commit_group;" ::: "memory");
    };

    issue_tile(0);

    for (int t = 0; t < NT; t++) {
        if (t + 1 < NT) {
            issue_tile(t + 1);
            asm volatile("cp.async.wait_group 1;" ::: "memory");
        } else {
            asm volatile("cp.async.wait_group 0;" ::: "memory");
        }
        __syncthreads();

        const uint32_t bb = (uint32_t)(t & 1) * BUF_BYTES;

#pragma unroll
        for (int k16 = 0; k16 < 4; k16++) {
            const int kb2 = k16 * 32;     // byte offset of this k16 step

            uint32_t bh[4][2], bl[4][2], af[4][4];
            // B fragments: 2 x ldmatrix.x4 covers 4 n8 groups
#pragma unroll
            for (int g = 0; g < 2; g++) {
                const uint32_t off =
                    sw128((uint32_t)((wn * 32 + g * 16 + b_row) * 128 + kb2 + b_kb));
                uint32_t r[4];
                ldsm4(r, sb + bb + SM_BH + off);
                bh[g*2][0] = r[0]; bh[g*2][1] = r[1];
                bh[g*2+1][0] = r[2]; bh[g*2+1][1] = r[3];
                ldsm4(r, sb + bb + SM_BL + off);
                bl[g*2][0] = r[0]; bl[g*2][1] = r[1];
                bl[g*2+1][0] = r[2]; bl[g*2+1][1] = r[3];
            }
            // A-hi fragments, then hh + hl products
#pragma unroll
            for (int mi = 0; mi < 4; mi++) {
                const uint32_t off =
                    sw128((uint32_t)((wm * 64 + mi * 16 + a_row) * 128 + kb2 + a_kb));
                ldsm4(af[mi], sb + bb + SM_AH + off);
            }
#pragma unroll
            for (int mi = 0; mi < 4; mi++)
#pragma unroll
                for (int ni = 0; ni < 4; ni++) {
                    mma_bf16(acc[mi][ni], af[mi], bh[ni]);
                    mma_bf16(acc[mi][ni], af[mi], bl[ni]);
                }
            // A-lo fragments, lh product
#pragma unroll
            for (int mi = 0; mi < 4; mi++) {
                const uint32_t off =
                    sw128((uint32_t)((wm * 64 + mi * 16 + a_row) * 128 + kb2 + a_kb));
                ldsm4(af[mi], sb + bb + SM_AL + off);
            }
#pragma unroll
            for (int mi = 0; mi < 4; mi++)
#pragma unroll
                for (int ni = 0; ni < 4; ni++)
                    mma_bf16(acc[mi][ni], af[mi], bh[ni]);
        }
        __syncthreads();
    }

    // ---- epilogue: fragment -> global fp32 (+bias) ----
    const int g   = lane >> 2;
    const int tig = lane & 3;
#pragma unroll
    for (int mi = 0; mi < 4; mi++) {
#pragma unroll
        for (int ni = 0; ni < 4; ni++) {
            const int row = m0 + wm * 64 + mi * 16 + g;
            const int col = n0 + wn * 32 + ni * 8 + tig * 2;
            float2 v0, v1;
            v0.x = acc[mi][ni][0]; v0.y = acc[mi][ni][1];
            v1.x = acc[mi][ni][2]; v1.y = acc[mi][ni][3];
            if (bias) {
                const float b0 = bias[col], b1 = bias[col + 1];
                v0.x += b0; v0.y += b1;
                v1.x += b0; v1.y += b1;
            }
            *(float2*)(C + (size_t)row * Ntot + col)       = v0;
            *(float2*)(C + (size_t)(row + 8) * Ntot + col) = v1;
        }
    }
}

// ---------------- fp32 -> bf16 hi/lo split (same layout) ---------------------
__global__ void split_kernel(const float* __restrict__ in,
                             __nv_bfloat16* __restrict__ hi,
                             __nv_bfloat16* __restrict__ lo, int n4)
{
    int i = blockIdx.x * blockDim.x + threadIdx.x;
    if (i >= n4) return;
    float4 v = ((const float4*)in)[i];
    __nv_bfloat16 h0 = __float2bfloat16(v.x);
    __nv_bfloat16 h1 = __float2bfloat16(v.y);
    __nv_bfloat16 h2 = __float2bfloat16(v.z);
    __nv_bfloat16 h3 = __float2bfloat16(v.w);
    __nv_bfloat162 H0, H1, L0, L1;
    H0.x = h0; H0.y = h1; H1.x = h2; H1.y = h3;
    L0.x = __float2bfloat16(v.x - __bfloat162float(h0));
    L0.y = __float2bfloat16(v.y - __bfloat162float(h1));
    L1.x = __float2bfloat16(v.z - __bfloat162float(h2));
    L1.y = __float2bfloat16(v.w - __bfloat162float(h3));
    ((__nv_bfloat162*)hi)[i * 2 + 0] = H0;
    ((__nv_bfloat162*)hi)[i * 2 + 1] = H1;
    ((__nv_bfloat162*)lo)[i * 2 + 0] = L0;
    ((__nv_bfloat162*)lo)[i * 2 + 1] = L1;
}

// ---------------- fp32 [K,N] -> bf16 hi/lo transposed [N,K] ------------------
__global__ void transpose_split_kernel(const float* __restrict__ W,
                                       __nv_bfloat16* __restrict__ Th,
                                       __nv_bfloat16* __restrict__ Tl,
                                       int K, int N)
{
    __shared__ float tile[32][33];
    const int n0 = blockIdx.x * 32;
    const int k0 = blockIdx.y * 32;
    const int tx = threadIdx.x;
    const int ty = threadIdx.y;           // 0..7
#pragma unroll
    for (int i = 0; i < 4; i++) {
        int k = k0 + ty + i * 8;
        tile[ty + i * 8][tx] = W[(size_t)k * N + n0 + tx];
    }
    __syncthreads();
#pragma unroll
    for (int i = 0; i < 4; i++) {
        int n = n0 + ty + i * 8;
        float v = tile[tx][ty + i * 8];
        __nv_bfloat16 h = __float2bfloat16(v);
        Th[(size_t)n * K + k0 + tx] = h;
        Tl[(size_t)n * K + k0 + tx] = __float2bfloat16(v - __bfloat162float(h));
    }
}

// ---------------- RoPE + scatter to [B*H, T, D] ------------------------------
__global__ void rope_scatter_kernel()
{
    int idx = blockIdx.x * blockDim.x + threadIdx.x;
    const int TOT = MTOT * 3 * HH * (DD / 2);
    if (idx >= TOT) return;

    int row = idx / 1536;            // b*T + t
    int c0  = idx % 1536;
    int sel = c0 / 512;              // 0=q 1=k 2=v
    int h   = (c0 % 512) / 32;
    int p   = c0 % 32;               // pair index (d = 2p, 2p+1)
    int t   = row % TT;
    int b   = row / TT;

    size_t src = (size_t)row * QKVN + sel * CC + h * DD + 2 * p;
    float x0 = g_qkv[src];
    float x1 = g_qkv[src + 1];

    float* dst = (sel == 0) ? g_q : (sel == 1) ? g_k : g_v;
    size_t o = ((size_t)(b * HH + h) * TT + t) * DD + 2 * p;

    if (sel < 2) {
        const float LN1E4_OVER_32 = 0.28782313662425572f;
        float inv_freq = __expf(-(float)p * LN1E4_OVER_32);
        float ang = (float)t * inv_freq;
        float s, c;
        sincosf(ang, &s, &c);
        dst[o]     = x0 * c - x1 * s;
        dst[o + 1] = x1 * c + x0 * s;
    } else {
        dst[o]     = x0;
        dst[o + 1] = x1;
    }
}

// ---------------- flash attention (fp32, causal, online softmax) --------------
// Writes bf16 hi/lo split output directly (consumed by the oproj HMMA GEMM).
#define AT_THREADS 256
#define AT_BQ 128        // queries per CTA
#define AT_BKT 64        // keys per SMEM tile
#define AT_CH 16         // keys per softmax chunk

__global__ __launch_bounds__(AT_THREADS)
void attn_kernel()
{
    __shared__ float Ks[AT_BKT][DD];
    __shared__ float Vs[AT_BKT][DD];

    const int bh   = blockIdx.y;             // b*16 + h
    const int q0   = blockIdx.x * AT_BQ;
    const int tid  = threadIdx.x;
    const int warp = tid >> 5;
    const int lane = tid & 31;
    const int qloc = lane & 15;              // query within warp
    const int dh   = lane >> 4;              // dim half: 0 or 1
    const int qi   = q0 + warp * 16 + qloc;
    const int dbase = dh * 32;

    const float* Qb = g_q + ((size_t)bh * TT + qi) * DD + dbase;
    const float* Kb = g_k + (size_t)bh * TT * DD;
    const float* Vb = g_v + (size_t)bh * TT * DD;

    float q[32];
#pragma unroll
    for (int d = 0; d < 32; d += 4) {
        float4 v = *(const float4*)(Qb + d);
        q[d + 0] = v.x * 0.125f;
        q[d + 1] = v.y * 0.125f;
        q[d + 2] = v.z * 0.125f;
        q[d + 3] = v.w * 0.125f;
    }

    float m = -INFINITY, l = 0.0f;
    float acc[32] = {};

    const int wqmax = q0 + warp * 16 + 15;   // warp's last query (uniform)
    const int kend  = q0 + AT_BQ;

    for (int j0 = 0; j0 < kend; j0 += AT_BKT) {
#pragma unroll
        for (int i = 0; i < (AT_BKT * DD / 4) / AT_THREADS; i++) {   // 4 iters
            int e = tid + i * AT_THREADS;
            ((float4*)&Ks[0][0])[e] = ((const float4*)(Kb + (size_t)j0 * DD))[e];
            ((float4*)&Vs[0][0])[e] = ((const float4*)(Vb + (size_t)j0 * DD))[e];
        }
        __syncthreads();

        for (int c0 = 0; c0 < AT_BKT; c0 += AT_CH) {
            const int kbase = j0 + c0;
            if (kbase > wqmax) break;        // warp-uniform

            float s[AT_CH];
#pragma unroll
            for (int j = 0; j < AT_CH; j++) {
                const float* kr = &Ks[c0 + j][dbase];
                float ps0 = 0.f, ps1 = 0.f, ps2 = 0.f, ps3 = 0.f;
#pragma unroll
                for (int d = 0; d < 32; d += 16) {
                    float4 a = *(const float4*)(kr + d + 0);
                    float4 b = *(const float4*)(kr + d + 4);
                    float4 c = *(const float4*)(kr + d + 8);
                    float4 e = *(const float4*)(kr + d + 12);
                    ps0 += q[d + 0]*a.x + q[d + 1]*a.y + q[d + 2]*a.z + q[d + 3]*a.w;
                    ps1 += q[d + 4]*b.x + q[d + 5]*b.y + q[d + 6]*b.z + q[d + 7]*b.w;
                    ps2 += q[d + 8]*c.x + q[d + 9]*c.y + q[d +10]*c.z + q[d +11]*c.w;
                    ps3 += q[d +12]*e.x + q[d +13]*e.y + q[d +14]*e.z + q[d +15]*e.w;
                }
                float part = (ps0 + ps1) + (ps2 + ps3);
                float full = part + __shfl_xor_sync(0xffffffffu, part, 16);
                s[j] = (kbase + j > qi) ? -INFINITY : full;
            }

            float mt = m;
#pragma unroll
            for (int j = 0; j < AT_CH; j++) mt = fmaxf(mt, s[j]);

            if (mt > -INFINITY) {
                float r = __expf(m - mt);
                l *= r;
#pragma unroll
                for (int d = 0; d < 32; d++) acc[d] *= r;
                m = mt;

#pragma unroll
                for (int j = 0; j < AT_CH; j++) {
                    float p = __expf(s[j] - m);
                    l += p;
                    const float* vr = &Vs[c0 + j][dbase];
#pragma unroll
                    for (int d = 0; d < 32; d += 4) {
                        float4 vv = *(const float4*)(vr + d);
                        acc[d + 0] += p * vv.x;
                        acc[d + 1] += p * vv.y;
                        acc[d + 2] += p * vv.z;
                        acc[d + 3] += p * vv.w;
                    }
                }
            }
        }
        __syncthreads();
    }

    // write bf16 hi/lo split directly: out[b, qi, h*64 + dbase + d]
    const int b = bh >> 4;
    const int h = bh & 15;
    const float inv = 1.0f / l;
    const size_t obase = ((size_t)(b * TT + qi)) * CC + h * DD + dbase;
#pragma unroll
    for (int d = 0; d < 32; d += 2) {
        float o0 = acc[d + 0] * inv;
        float o1 = acc[d + 1] * inv;
        __nv_bfloat162 H, L;
        H.x = __float2bfloat16(o0);
        H.y = __float2bfloat16(o1);
        L.x = __float2bfloat16(o0 - __bfloat162float(H.x));
        L.y = __float2bfloat16(o1 - __bfloat162float(H.y));
        *(__nv_bfloat162*)(g_ath + obase + d) = H;
        *(__nv_bfloat162*)(g_atl + obase + d) = L;
    }
}

// ---------------- launch ------------------------------------------------------
extern "C" void kernel_launch(void* const* d_in, const int* in_sizes, int n_in,
                              void* d_out, int out_size)
{
    const float* x    = (const float*)d_in[0];
    const float* Wqkv = (const float*)d_in[1];
    const float* Wo   = (const float*)d_in[2];
    const float* bo   = (const float*)d_in[3];
    float* out = (float*)d_out;

    (void)in_sizes; (void)n_in; (void)out_size;

    static int smem_set = 0;
    if (!smem_set) {
        cudaFuncSetAttribute(mm_bf16_kernel,
                             cudaFuncAttributeMaxDynamicSharedMemorySize, SM_TOTAL);
        smem_set = 1;
    }

    __nv_bfloat16 *xh, *xl, *wqh, *wql, *ath, *atl, *woh, *wol;
    cudaGetSymbolAddress((void**)&xh,  g_xh);
    cudaGetSymbolAddress((void**)&xl,  g_xl);
    cudaGetSymbolAddress((void**)&wqh, g_wqkvTh);
    cudaGetSymbolAddress((void**)&wql, g_wqkvTl);
    cudaGetSymbolAddress((void**)&ath, g_ath);
    cudaGetSymbolAddress((void**)&atl, g_atl);
    cudaGetSymbolAddress((void**)&woh, g_woTh);
    cudaGetSymbolAddress((void**)&wol, g_woTl);
    float* qkvp;
    cudaGetSymbolAddress((void**)&qkvp, g_qkv);

    // 1) split x to bf16 hi/lo
    {
        int n4 = MTOT * CC / 4;
        split_kernel<<<(n4 + 255) / 256, 256>>>(x, xh, xl, n4);
    }
    // 2) transpose+split Wqkv -> [3072,1024]
    {
        dim3 grid(QKVN / 32, CC / 32);
        transpose_split_kernel<<<grid, dim3(32, 8)>>>(Wqkv, wqh, wql, CC, QKVN);
    }
    // 3) QKV GEMM (HMMA): [4096,1024] x [3072,1024]^T
    {
        dim3 grid(QKVN / 128, MTOT / 128);   // (24, 32)
        mm_bf16_kernel<<<grid, MM_THREADS, SM_TOTAL>>>(
            xh, xl, wqh, wql, nullptr, qkvp, QKVN, CC);
    }
    // 4) RoPE + scatter
    {
        int tot = MTOT * 3 * HH * (DD / 2);
        rope_scatter_kernel<<<(tot + 255) / 256, 256>>>();
    }
    // 5) causal flash attention (writes bf16 hi/lo att output)
    {
        dim3 grid(TT / AT_BQ, BB * HH);
        attn_kernel<<<grid, AT_THREADS>>>();
    }
    // 6) transpose+split Wo -> [1024,1024]
    {
        dim3 grid(CC / 32, CC / 32);
        transpose_split_kernel<<<grid, dim3(32, 8)>>>(Wo, woh, wol, CC, CC);
    }
    // 7) output projection (HMMA) + bias
    {
        dim3 grid(CC / 128, MTOT / 128);     // (8, 32)
        mm_bf16_kernel<<<grid, MM_THREADS, SM_TOTAL>>>(
            ath, atl, woh, wol, bo, out, CC, CC);
    }
}

// round 7
// speedup vs baseline: 3.4783x; 2.0750x over previous
#include <cuda_runtime.h>
#include <cuda_bf16.h>
#include <math.h>
#include <stdint.h>

// Problem constants
#define BB   2
#define TT   2048
#define CC   1024
#define HH   16
#define DD   64
#define MTOT (BB*TT)          // 4096
#define QKVN (3*CC)           // 3072

// ---------------- scratch (device globals; no allocs allowed) ----------------
__device__ float g_qkv[(size_t)MTOT * QKVN];      // 4096 x 3072

// bf16 split operands
__device__ __nv_bfloat16 g_xh[(size_t)MTOT * CC];       // x hi
__device__ __nv_bfloat16 g_xl[(size_t)MTOT * CC];       // x lo
__device__ __nv_bfloat16 g_wqkvTh[(size_t)QKVN * CC];   // Wqkv^T hi  [N,K]
__device__ __nv_bfloat16 g_wqkvTl[(size_t)QKVN * CC];
__device__ __nv_bfloat16 g_ath[(size_t)MTOT * CC];      // attention out hi
__device__ __nv_bfloat16 g_atl[(size_t)MTOT * CC];      // attention out lo
__device__ __nv_bfloat16 g_woTh[(size_t)CC * CC];       // Wo^T hi    [N,K]
__device__ __nv_bfloat16 g_woTl[(size_t)CC * CC];

// attention operands, hi/lo split
__device__ __nv_bfloat16 g_qh[(size_t)BB*HH*TT*DD];     // [BH, T, D] (scaled)
__device__ __nv_bfloat16 g_ql[(size_t)BB*HH*TT*DD];
__device__ __nv_bfloat16 g_kh[(size_t)BB*HH*TT*DD];     // [BH, T, D]
__device__ __nv_bfloat16 g_kl[(size_t)BB*HH*TT*DD];
__device__ __nv_bfloat16 g_vth[(size_t)BB*HH*DD*TT];    // [BH, D, T]  (V^T)
__device__ __nv_bfloat16 g_vtl[(size_t)BB*HH*DD*TT];

// ---------------- helpers -----------------------------------------------------
__device__ __forceinline__ uint32_t smem_u32(const void* p) {
    uint32_t a;
    asm("{ .reg .u64 t; cvta.to.shared.u64 t, %1; cvt.u32.u64 %0, t; }"
        : "=r"(a) : "l"(p));
    return a;
}
__device__ __forceinline__ uint32_t sw128(uint32_t b) { return b ^ ((b >> 3) & 0x70); }

__device__ __forceinline__ void ldsm4(uint32_t* r, uint32_t addr) {
    asm volatile("ldmatrix.sync.aligned.m8n8.x4.shared.b16 {%0,%1,%2,%3}, [%4];"
                 : "=r"(r[0]), "=r"(r[1]), "=r"(r[2]), "=r"(r[3]) : "r"(addr));
}
__device__ __forceinline__ void mma_bf16(float* c, const uint32_t* a, const uint32_t* b) {
    asm volatile(
        "mma.sync.aligned.m16n8k16.row.col.f32.bf16.bf16.f32 "
        "{%0,%1,%2,%3}, {%4,%5,%6,%7}, {%8,%9}, {%0,%1,%2,%3};"
        : "+f"(c[0]), "+f"(c[1]), "+f"(c[2]), "+f"(c[3])
        : "r"(a[0]), "r"(a[1]), "r"(a[2]), "r"(a[3]), "r"(b[0]), "r"(b[1]));
}
__device__ __forceinline__ void cpasync16(uint32_t dst, const void* src) {
    asm volatile("cp.async.cg.shared.global [%0], [%1], 16;"
                 :: "r"(dst), "l"(src) : "memory");
}
#define CP_COMMIT() asm volatile("cp.async.commit_group;" ::: "memory")
#define CP_WAIT(n)  asm volatile("cp.async.wait_group %0;" :: "n"(n) : "memory")

__device__ __forceinline__ void split_bf16(float v, __nv_bfloat16& h, __nv_bfloat16& l) {
    h = __float2bfloat16(v);
    l = __float2bfloat16(v - __bfloat162float(h));
}
// pack (x,y) into bf16x2 hi word; residual into lo word
__device__ __forceinline__ void pack_split2(float x, float y, uint32_t& hi, uint32_t& lo) {
    __nv_bfloat162 H, L;
    H.x = __float2bfloat16(x);
    H.y = __float2bfloat16(y);
    L.x = __float2bfloat16(x - __bfloat162float(H.x));
    L.y = __float2bfloat16(y - __bfloat162float(H.y));
    hi = *reinterpret_cast<uint32_t*>(&H);
    lo = *reinterpret_cast<uint32_t*>(&L);
}

// ---------------- HMMA split-bf16 GEMM: C[M,Ntot] = A@B^T (+bias) ------------
#define MM_THREADS 256
#define SM_AH 0
#define SM_AL 16384
#define SM_BH 32768
#define SM_BL 49152
#define BUF_BYTES 65536
#define SM_TOTAL (2*BUF_BYTES)            // 131072

__global__ __launch_bounds__(MM_THREADS)
void mm_bf16_kernel(const __nv_bfloat16* __restrict__ Ah,
                    const __nv_bfloat16* __restrict__ Al,
                    const __nv_bfloat16* __restrict__ Bh,
                    const __nv_bfloat16* __restrict__ Bl,
                    const float* __restrict__ bias,
                    float* __restrict__ C,
                    int Ntot, int K)
{
    extern __shared__ __align__(1024) char smem[];
    const uint32_t sb = smem_u32(smem);
    const int tid  = threadIdx.x;
    const int wid  = tid >> 5;
    const int lane = tid & 31;
    const int m0 = blockIdx.y * 128;
    const int n0 = blockIdx.x * 128;
    const int wm = wid >> 2;
    const int wn = wid & 3;

    const int a_row = (lane & 7) | (((lane >> 3) & 1) << 3);
    const int a_kb  = (lane >> 4) * 16;
    const int b_row = (lane & 7) | ((lane >> 4) << 3);
    const int b_kb  = ((lane >> 3) & 1) * 16;

    const int cr = tid >> 3;
    const int cc = tid & 7;
    const uint32_t so_base = (uint32_t)(cr * 128 + cc * 16);

    float acc[4][4][4] = {};

    const int NT = K / 64;

    auto issue_tile = [&](int t) {
        const int k0 = t * 64;
        const uint32_t bb = (uint32_t)(t & 1) * BUF_BYTES;
#pragma unroll
        for (int i = 0; i < 4; i++) {
            const int r = cr + i * 32;
            const uint32_t so = sw128(so_base + (uint32_t)i * 32 * 128);
            const size_t aoff = (size_t)(m0 + r) * K + k0 + cc * 8;
            const size_t boff = (size_t)(n0 + r) * K + k0 + cc * 8;
            cpasync16(sb + bb + SM_AH + so, Ah + aoff);
            cpasync16(sb + bb + SM_AL + so, Al + aoff);
            cpasync16(sb + bb + SM_BH + so, Bh + boff);
            cpasync16(sb + bb + SM_BL + so, Bl + boff);
        }
        CP_COMMIT();
    };

    issue_tile(0);

    for (int t = 0; t < NT; t++) {
        if (t + 1 < NT) {
            issue_tile(t + 1);
            CP_WAIT(1);
        } else {
            CP_WAIT(0);
        }
        __syncthreads();

        const uint32_t bb = (uint32_t)(t & 1) * BUF_BYTES;

#pragma unroll
        for (int k16 = 0; k16 < 4; k16++) {
            const int kb2 = k16 * 32;

            uint32_t bh[4][2], bl[4][2], af[4][4];
#pragma unroll
            for (int g = 0; g < 2; g++) {
                const uint32_t off =
                    sw128((uint32_t)((wn * 32 + g * 16 + b_row) * 128 + kb2 + b_kb));
                uint32_t r[4];
                ldsm4(r, sb + bb + SM_BH + off);
                bh[g*2][0] = r[0]; bh[g*2][1] = r[1];
                bh[g*2+1][0] = r[2]; bh[g*2+1][1] = r[3];
                ldsm4(r, sb + bb + SM_BL + off);
                bl[g*2][0] = r[0]; bl[g*2][1] = r[1];
                bl[g*2+1][0] = r[2]; bl[g*2+1][1] = r[3];
            }
#pragma unroll
            for (int mi = 0; mi < 4; mi++) {
                const uint32_t off =
                    sw128((uint32_t)((wm * 64 + mi * 16 + a_row) * 128 + kb2 + a_kb));
                ldsm4(af[mi], sb + bb + SM_AH + off);
            }
#pragma unroll
            for (int mi = 0; mi < 4; mi++)
#pragma unroll
                for (int ni = 0; ni < 4; ni++) {
                    mma_bf16(acc[mi][ni], af[mi], bh[ni]);
                    mma_bf16(acc[mi][ni], af[mi], bl[ni]);
                }
#pragma unroll
            for (int mi = 0; mi < 4; mi++) {
                const uint32_t off =
                    sw128((uint32_t)((wm * 64 + mi * 16 + a_row) * 128 + kb2 + a_kb));
                ldsm4(af[mi], sb + bb + SM_AL + off);
            }
#pragma unroll
            for (int mi = 0; mi < 4; mi++)
#pragma unroll
                for (int ni = 0; ni < 4; ni++)
                    mma_bf16(acc[mi][ni], af[mi], bh[ni]);
        }
        __syncthreads();
    }

    const int g   = lane >> 2;
    const int tig = lane & 3;
#pragma unroll
    for (int mi = 0; mi < 4; mi++) {
#pragma unroll
        for (int ni = 0; ni < 4; ni++) {
            const int row = m0 + wm * 64 + mi * 16 + g;
            const int col = n0 + wn * 32 + ni * 8 + tig * 2;
            float2 v0, v1;
            v0.x = acc[mi][ni][0]; v0.y = acc[mi][ni][1];
            v1.x = acc[mi][ni][2]; v1.y = acc[mi][ni][3];
            if (bias) {
                const float b0 = bias[col], b1 = bias[col + 1];
                v0.x += b0; v0.y += b1;
                v1.x += b0; v1.y += b1;
            }
            *(float2*)(C + (size_t)row * Ntot + col)       = v0;
            *(float2*)(C + (size_t)(row + 8) * Ntot + col) = v1;
        }
    }
}

// ---------------- fp32 -> bf16 hi/lo split ------------------------------------
__global__ void split_kernel(const float* __restrict__ in,
                             __nv_bfloat16* __restrict__ hi,
                             __nv_bfloat16* __restrict__ lo, int n4)
{
    int i = blockIdx.x * blockDim.x + threadIdx.x;
    if (i >= n4) return;
    float4 v = ((const float4*)in)[i];
    __nv_bfloat162 H0, H1, L0, L1;
    split_bf16(v.x, H0.x, L0.x);
    split_bf16(v.y, H0.y, L0.y);
    split_bf16(v.z, H1.x, L1.x);
    split_bf16(v.w, H1.y, L1.y);
    ((__nv_bfloat162*)hi)[i * 2 + 0] = H0;
    ((__nv_bfloat162*)hi)[i * 2 + 1] = H1;
    ((__nv_bfloat162*)lo)[i * 2 + 0] = L0;
    ((__nv_bfloat162*)lo)[i * 2 + 1] = L1;
}

// ---------------- fp32 [K,N] -> bf16 hi/lo transposed [N,K] ------------------
__global__ void transpose_split_kernel(const float* __restrict__ W,
                                       __nv_bfloat16* __restrict__ Th,
                                       __nv_bfloat16* __restrict__ Tl,
                                       int K, int N)
{
    __shared__ float tile[32][33];
    const int n0 = blockIdx.x * 32;
    const int k0 = blockIdx.y * 32;
    const int tx = threadIdx.x;
    const int ty = threadIdx.y;
#pragma unroll
    for (int i = 0; i < 4; i++) {
        int k = k0 + ty + i * 8;
        tile[ty + i * 8][tx] = W[(size_t)k * N + n0 + tx];
    }
    __syncthreads();
#pragma unroll
    for (int i = 0; i < 4; i++) {
        int n = n0 + ty + i * 8;
        float v = tile[tx][ty + i * 8];
        __nv_bfloat16 h, l;
        split_bf16(v, h, l);
        Th[(size_t)n * K + k0 + tx] = h;
        Tl[(size_t)n * K + k0 + tx] = l;
    }
}

// ---------------- RoPE + scatter into split bf16 attention operands ----------
__global__ void rope_scatter_kernel()
{
    int idx = blockIdx.x * blockDim.x + threadIdx.x;
    const int TOT = MTOT * 3 * HH * (DD / 2);
    if (idx >= TOT) return;

    int row = idx / 1536;            // b*T + t
    int c0  = idx % 1536;
    int sel = c0 / 512;              // 0=q 1=k 2=v
    int h   = (c0 % 512) / 32;
    int p   = c0 % 32;               // pair index (d = 2p, 2p+1)
    int t   = row % TT;
    int b   = row / TT;
    int bh  = b * HH + h;

    size_t src = (size_t)row * QKVN + sel * CC + h * DD + 2 * p;
    float x0 = g_qkv[src];
    float x1 = g_qkv[src + 1];

    if (sel == 2) {
        // V^T layout [BH, D, T]
        __nv_bfloat16 h0, l0, h1, l1;
        split_bf16(x0, h0, l0);
        split_bf16(x1, h1, l1);
        size_t o0 = ((size_t)bh * DD + 2 * p) * TT + t;
        size_t o1 = o0 + TT;
        g_vth[o0] = h0; g_vtl[o0] = l0;
        g_vth[o1] = h1; g_vtl[o1] = l1;
        return;
    }

    const float LN1E4_OVER_32 = 0.28782313662425572f;
    float inv_freq = __expf(-(float)p * LN1E4_OVER_32);
    float ang = (float)t * inv_freq;
    float s, c;
    sincosf(ang, &s, &c);
    float r0 = x0 * c - x1 * s;
    float r1 = x1 * c + x0 * s;

    size_t o = ((size_t)bh * TT + t) * DD + 2 * p;
    if (sel == 0) {
        r0 *= 0.125f; r1 *= 0.125f;     // fold in D^-0.5
        __nv_bfloat162 H, L;
        split_bf16(r0, H.x, L.x);
        split_bf16(r1, H.y, L.y);
        *(__nv_bfloat162*)(g_qh + o) = H;
        *(__nv_bfloat162*)(g_ql + o) = L;
    } else {
        __nv_bfloat162 H, L;
        split_bf16(r0, H.x, L.x);
        split_bf16(r1, H.y, L.y);
        *(__nv_bfloat162*)(g_kh + o) = H;
        *(__nv_bfloat162*)(g_kl + o) = L;
    }
}

// ---------------- flash attention on HMMA (split bf16, causal) ----------------
// CTA: 128 queries x 1 head. 8 warps, warp = 16 query rows (m16).
// Key tiles of 64; K [key,d] and V^T [d,key] staged hi/lo via cp.async.
#define FA_THREADS 256
#define FQ_H 0
#define FQ_L 16384
#define FKV  32768
#define FK_H 0
#define FK_L 8192
#define FV_H 16384
#define FV_L 24576
#define FA_BUF 32768
#define FA_SMEM (FKV + 2*FA_BUF)          // 98304

__global__ __launch_bounds__(FA_THREADS)
void attn_mma_kernel()
{
    extern __shared__ __align__(1024) char smem[];
    const uint32_t sb = smem_u32(smem);
    const int tid  = threadIdx.x;
    const int wid  = tid >> 5;
    const int lane = tid & 31;
    const int bh = blockIdx.y;
    const int qb = blockIdx.x;
    const int q0 = qb * 128;
    const int g   = lane >> 2;
    const int tig = lane & 3;

    const int a_row = (lane & 7) | (((lane >> 3) & 1) << 3);
    const int a_kb  = (lane >> 4) * 16;
    const int b_row = (lane & 7) | ((lane >> 4) << 3);
    const int b_kb  = ((lane >> 3) & 1) * 16;

    const __nv_bfloat16* Qh = g_qh + (size_t)bh * TT * DD;
    const __nv_bfloat16* Ql = g_ql + (size_t)bh * TT * DD;
    const __nv_bfloat16* Kh = g_kh + (size_t)bh * TT * DD;
    const __nv_bfloat16* Kl = g_kl + (size_t)bh * TT * DD;
    const __nv_bfloat16* Vh = g_vth + (size_t)bh * DD * TT;
    const __nv_bfloat16* Vl = g_vtl + (size_t)bh * DD * TT;

    const int cr = tid >> 3;              // 0..31
    const int cc = tid & 7;

    // stage Q tile (128 x 64, hi/lo) — group A with key-tile 0
    {
#pragma unroll
        for (int i = 0; i < 4; i++) {
            const int r = cr + i * 32;
            const uint32_t so = sw128((uint32_t)(r * 128 + cc * 16));
            const size_t off = (size_t)(q0 + r) * DD + cc * 8;
            cpasync16(sb + FQ_H + so, Qh + off);
            cpasync16(sb + FQ_L + so, Ql + off);
        }
    }

    auto issue_tile = [&](int t) {
        const int jt = t * 64;
        const uint32_t bb = sb + FKV + (uint32_t)(t & 1) * FA_BUF;
#pragma unroll
        for (int i = 0; i < 2; i++) {
            const int r = cr + i * 32;    // 0..63
            const uint32_t so = sw128((uint32_t)(r * 128 + cc * 16));
            cpasync16(bb + FK_H + so, Kh + (size_t)(jt + r) * DD + cc * 8);
            cpasync16(bb + FK_L + so, Kl + (size_t)(jt + r) * DD + cc * 8);
            cpasync16(bb + FV_H + so, Vh + (size_t)r * TT + jt + cc * 8);
            cpasync16(bb + FV_L + so, Vl + (size_t)r * TT + jt + cc * 8);
        }
        CP_COMMIT();
    };

    issue_tile(0);                        // Q + tile0 = group A

    const int NTL = qb * 2 + 2;           // tiles to process
    const int wqmin = q0 + wid * 16;
    const int wqmax = wqmin + 15;
    const int r0 = wqmin + g;             // this thread's query rows
    const int r1 = r0 + 8;

    float o[8][4] = {};
    float m0 = -1e30f, m1 = -1e30f, l0 = 0.0f, l1 = 0.0f;
    uint32_t qfh[4][4], qfl[4][4];

    for (int t = 0; t < NTL; t++) {
        if (t + 1 < NTL) {
            issue_tile(t + 1);
            CP_WAIT(1);
        } else {
            CP_WAIT(0);
        }
        __syncthreads();

        if (t == 0) {
            // load Q fragments (once)
#pragma unroll
            for (int k16 = 0; k16 < 4; k16++) {
                const uint32_t off =
                    sw128((uint32_t)((wid * 16 + a_row) * 128 + k16 * 32 + a_kb));
                ldsm4(qfh[k16], sb + FQ_H + off);
                ldsm4(qfl[k16], sb + FQ_L + off);
            }
        }

        const int jt = t * 64;
        if (jt <= wqmax) {
            const uint32_t bb = sb + FKV + (uint32_t)(t & 1) * FA_BUF;

            // ---- S = Q K^T (split) ----
            float s[8][4] = {};
#pragma unroll
            for (int g2 = 0; g2 < 4; g2++) {
#pragma unroll
                for (int k16 = 0; k16 < 4; k16++) {
                    const uint32_t off =
                        sw128((uint32_t)((g2 * 16 + b_row) * 128 + k16 * 32 + b_kb));
                    uint32_t rbh[4], rbl[4];
                    ldsm4(rbh, bb + FK_H + off);
                    ldsm4(rbl, bb + FK_L + off);
                    mma_bf16(s[g2*2],   qfh[k16], rbh);
                    mma_bf16(s[g2*2+1], qfh[k16], rbh + 2);
                    mma_bf16(s[g2*2],   qfh[k16], rbl);
                    mma_bf16(s[g2*2+1], qfh[k16], rbl + 2);
                    mma_bf16(s[g2*2],   qfl[k16], rbh);
                    mma_bf16(s[g2*2+1], qfl[k16], rbh + 2);
                }
            }

            // ---- causal mask ----
            if (jt + 63 > wqmin) {
#pragma unroll
                for (int st = 0; st < 8; st++) {
                    const int k = jt + st * 8 + tig * 2;
                    if (k     > r0) s[st][0] = -1e30f;
                    if (k + 1 > r0) s[st][1] = -1e30f;
                    if (k     > r1) s[st][2] = -1e30f;
                    if (k + 1 > r1) s[st][3] = -1e30f;
                }
            }

            // ---- online softmax ----
            float mx0 = -1e30f, mx1 = -1e30f;
#pragma unroll
            for (int st = 0; st < 8; st++) {
                mx0 = fmaxf(mx0, fmaxf(s[st][0], s[st][1]));
                mx1 = fmaxf(mx1, fmaxf(s[st][2], s[st][3]));
            }
            mx0 = fmaxf(mx0, __shfl_xor_sync(0xffffffffu, mx0, 1));
            mx0 = fmaxf(mx0, __shfl_xor_sync(0xffffffffu, mx0, 2));
            mx1 = fmaxf(mx1, __shfl_xor_sync(0xffffffffu, mx1, 1));
            mx1 = fmaxf(mx1, __shfl_xor_sync(0xffffffffu, mx1, 2));

            const float mt0 = fmaxf(m0, mx0);
            const float mt1 = fmaxf(m1, mx1);
            const float rs0 = __expf(m0 - mt0);
            const float rs1 = __expf(m1 - mt1);
            l0 *= rs0; l1 *= rs1;
            m0 = mt0;  m1 = mt1;
#pragma unroll
            for (int st = 0; st < 8; st++) {
                o[st][0] *= rs0; o[st][1] *= rs0;
                o[st][2] *= rs1; o[st][3] *= rs1;
            }

            float ps0 = 0.0f, ps1 = 0.0f;
#pragma unroll
            for (int st = 0; st < 8; st++) {
                s[st][0] = __expf(s[st][0] - m0);
                s[st][1] = __expf(s[st][1] - m0);
                s[st][2] = __expf(s[st][2] - m1);
                s[st][3] = __expf(s[st][3] - m1);
                ps0 += s[st][0] + s[st][1];
                ps1 += s[st][2] + s[st][3];
            }
            ps0 += __shfl_xor_sync(0xffffffffu, ps0, 1);
            ps0 += __shfl_xor_sync(0xffffffffu, ps0, 2);
            ps1 += __shfl_xor_sync(0xffffffffu, ps1, 1);
            ps1 += __shfl_xor_sync(0xffffffffu, ps1, 2);
            l0 += ps0; l1 += ps1;

            // ---- O += P V (split) ----
#pragma unroll
            for (int k16 = 0; k16 < 4; k16++) {
                uint32_t ah[4], al[4];
                pack_split2(s[2*k16][0],   s[2*k16][1],   ah[0], al[0]);
                pack_split2(s[2*k16][2],   s[2*k16][3],   ah[1], al[1]);
                pack_split2(s[2*k16+1][0], s[2*k16+1][1], ah[2], al[2]);
                pack_split2(s[2*k16+1][2], s[2*k16+1][3], ah[3], al[3]);
#pragma unroll
                for (int g2 = 0; g2 < 4; g2++) {
                    const uint32_t off =
                        sw128((uint32_t)((g2 * 16 + b_row) * 128 + k16 * 32 + b_kb));
                    uint32_t vbh[4], vbl[4];
                    ldsm4(vbh, bb + FV_H + off);
                    ldsm4(vbl, bb + FV_L + off);
                    mma_bf16(o[g2*2],   ah, vbh);
                    mma_bf16(o[g2*2+1], ah, vbh + 2);
                    mma_bf16(o[g2*2],   ah, vbl);
                    mma_bf16(o[g2*2+1], ah, vbl + 2);
                    mma_bf16(o[g2*2],   al, vbh);
                    mma_bf16(o[g2*2+1], al, vbh + 2);
                }
            }
        }
        __syncthreads();
    }

    // ---- epilogue: write split bf16 att output [B, T, C] ----
    const int b = bh >> 4;
    const int h = bh & 15;
    const float inv0 = 1.0f / l0;
    const float inv1 = 1.0f / l1;
    const size_t row0 = ((size_t)(b * TT + r0)) * CC + h * DD;
    const size_t row1 = ((size_t)(b * TT + r1)) * CC + h * DD;
#pragma unroll
    for (int st = 0; st < 8; st++) {
        const int col = st * 8 + tig * 2;
        uint32_t hi0, lo0, hi1, lo1;
        pack_split2(o[st][0] * inv0, o[st][1] * inv0, hi0, lo0);
        pack_split2(o[st][2] * inv1, o[st][3] * inv1, hi1, lo1);
        *(uint32_t*)(g_ath + row0 + col) = hi0;
        *(uint32_t*)(g_atl + row0 + col) = lo0;
        *(uint32_t*)(g_ath + row1 + col) = hi1;
        *(uint32_t*)(g_atl + row1 + col) = lo1;
    }
}

// ---------------- launch ------------------------------------------------------
extern "C" void kernel_launch(void* const* d_in, const int* in_sizes, int n_in,
                              void* d_out, int out_size)
{
    const float* x    = (const float*)d_in[0];
    const float* Wqkv = (const float*)d_in[1];
    const float* Wo   = (const float*)d_in[2];
    const float* bo   = (const float*)d_in[3];
    float* out = (float*)d_out;

    (void)in_sizes; (void)n_in; (void)out_size;

    static int smem_set = 0;
    if (!smem_set) {
        cudaFuncSetAttribute(mm_bf16_kernel,
                             cudaFuncAttributeMaxDynamicSharedMemorySize, SM_TOTAL);
        cudaFuncSetAttribute(attn_mma_kernel,
                             cudaFuncAttributeMaxDynamicSharedMemorySize, FA_SMEM);
        smem_set = 1;
    }

    __nv_bfloat16 *xh, *xl, *wqh, *wql, *ath, *atl, *woh, *wol;
    cudaGetSymbolAddress((void**)&xh,  g_xh);
    cudaGetSymbolAddress((void**)&xl,  g_xl);
    cudaGetSymbolAddress((void**)&wqh, g_wqkvTh);
    cudaGetSymbolAddress((void**)&wql, g_wqkvTl);
    cudaGetSymbolAddress((void**)&ath, g_ath);
    cudaGetSymbolAddress((void**)&atl, g_atl);
    cudaGetSymbolAddress((void**)&woh, g_woTh);
    cudaGetSymbolAddress((void**)&wol, g_woTl);
    float* qkvp;
    cudaGetSymbolAddress((void**)&qkvp, g_qkv);

    // 1) split x to bf16 hi/lo
    {
        int n4 = MTOT * CC / 4;
        split_kernel<<<(n4 + 255) / 256, 256>>>(x, xh, xl, n4);
    }
    // 2) transpose+split Wqkv -> [3072,1024]
    {
        dim3 grid(QKVN / 32, CC / 32);
        transpose_split_kernel<<<grid, dim3(32, 8)>>>(Wqkv, wqh, wql, CC, QKVN);
    }
    // 3) QKV GEMM (HMMA)
    {
        dim3 grid(QKVN / 128, MTOT / 128);
        mm_bf16_kernel<<<grid, MM_THREADS, SM_TOTAL>>>(
            xh, xl, wqh, wql, nullptr, qkvp, QKVN, CC);
    }
    // 4) RoPE + scatter into split attention operands
    {
        int tot = MTOT * 3 * HH * (DD / 2);
        rope_scatter_kernel<<<(tot + 255) / 256, 256>>>();
    }
    // 5) causal flash attention on tensor cores
    {
        dim3 grid(TT / 128, BB * HH);
        attn_mma_kernel<<<grid, FA_THREADS, FA_SMEM>>>();
    }
    // 6) transpose+split Wo
    {
        dim3 grid(CC / 32, CC / 32);
        transpose_split_kernel<<<grid, dim3(32, 8)>>>(Wo, woh, wol, CC, CC);
    }
    // 7) output projection (HMMA) + bias
    {
        dim3 grid(CC / 128, MTOT / 128);
        mm_bf16_kernel<<<grid, MM_THREADS, SM_TOTAL>>>(
            ath, atl, woh, wol, bo, out, CC, CC);
    }
}

// round 8
// speedup vs baseline: 3.7433x; 1.0762x over previous
#include <cuda_runtime.h>
#include <cuda_bf16.h>
#include <math.h>
#include <stdint.h>

// Problem constants
#define BB   2
#define TT   2048
#define CC   1024
#define HH   16
#define DD   64
#define MTOT (BB*TT)          // 4096
#define QKVN (3*CC)           // 3072

// ---------------- scratch (device globals; no allocs allowed) ----------------
__device__ float g_qkv[(size_t)MTOT * QKVN];      // 4096 x 3072

// bf16 split operands
__device__ __nv_bfloat16 g_xh[(size_t)MTOT * CC];       // x hi
__device__ __nv_bfloat16 g_xl[(size_t)MTOT * CC];       // x lo
__device__ __nv_bfloat16 g_wqkvTh[(size_t)QKVN * CC];   // Wqkv^T hi  [N,K]
__device__ __nv_bfloat16 g_wqkvTl[(size_t)QKVN * CC];
__device__ __nv_bfloat16 g_ath[(size_t)MTOT * CC];      // attention out hi
__device__ __nv_bfloat16 g_atl[(size_t)MTOT * CC];      // attention out lo
__device__ __nv_bfloat16 g_woTh[(size_t)CC * CC];       // Wo^T hi    [N,K]
__device__ __nv_bfloat16 g_woTl[(size_t)CC * CC];

// attention operands, hi/lo split — ALL in [BH, T, D] layout
__device__ __nv_bfloat16 g_qh[(size_t)BB*HH*TT*DD];     // (scaled by D^-0.5)
__device__ __nv_bfloat16 g_ql[(size_t)BB*HH*TT*DD];
__device__ __nv_bfloat16 g_kh[(size_t)BB*HH*TT*DD];
__device__ __nv_bfloat16 g_kl[(size_t)BB*HH*TT*DD];
__device__ __nv_bfloat16 g_vh[(size_t)BB*HH*TT*DD];
__device__ __nv_bfloat16 g_vl[(size_t)BB*HH*TT*DD];

// ---------------- helpers -----------------------------------------------------
__device__ __forceinline__ uint32_t smem_u32(const void* p) {
    uint32_t a;
    asm("{ .reg .u64 t; cvta.to.shared.u64 t, %1; cvt.u32.u64 %0, t; }"
        : "=r"(a) : "l"(p));
    return a;
}
__device__ __forceinline__ uint32_t sw128(uint32_t b) { return b ^ ((b >> 3) & 0x70); }

__device__ __forceinline__ void ldsm4(uint32_t* r, uint32_t addr) {
    asm volatile("ldmatrix.sync.aligned.m8n8.x4.shared.b16 {%0,%1,%2,%3}, [%4];"
                 : "=r"(r[0]), "=r"(r[1]), "=r"(r[2]), "=r"(r[3]) : "r"(addr));
}
__device__ __forceinline__ void ldsm4t(uint32_t* r, uint32_t addr) {
    asm volatile("ldmatrix.sync.aligned.m8n8.x4.trans.shared.b16 {%0,%1,%2,%3}, [%4];"
                 : "=r"(r[0]), "=r"(r[1]), "=r"(r[2]), "=r"(r[3]) : "r"(addr));
}
__device__ __forceinline__ void mma_bf16(float* c, const uint32_t* a, const uint32_t* b) {
    asm volatile(
        "mma.sync.aligned.m16n8k16.row.col.f32.bf16.bf16.f32 "
        "{%0,%1,%2,%3}, {%4,%5,%6,%7}, {%8,%9}, {%0,%1,%2,%3};"
        : "+f"(c[0]), "+f"(c[1]), "+f"(c[2]), "+f"(c[3])
        : "r"(a[0]), "r"(a[1]), "r"(a[2]), "r"(a[3]), "r"(b[0]), "r"(b[1]));
}
__device__ __forceinline__ void cpasync16(uint32_t dst, const void* src) {
    asm volatile("cp.async.cg.shared.global [%0], [%1], 16;"
                 :: "r"(dst), "l"(src) : "memory");
}
#define CP_COMMIT() asm volatile("cp.async.commit_group;" ::: "memory")
#define CP_WAIT(n)  asm volatile("cp.async.wait_group %0;" :: "n"(n) : "memory")

__device__ __forceinline__ void split_bf16(float v, __nv_bfloat16& h, __nv_bfloat16& l) {
    h = __float2bfloat16(v);
    l = __float2bfloat16(v - __bfloat162float(h));
}
__device__ __forceinline__ void pack_split2(float x, float y, uint32_t& hi, uint32_t& lo) {
    __nv_bfloat162 H, L;
    H.x = __float2bfloat16(x);
    H.y = __float2bfloat16(y);
    L.x = __float2bfloat16(x - __bfloat162float(H.x));
    L.y = __float2bfloat16(y - __bfloat162float(H.y));
    hi = *reinterpret_cast<uint32_t*>(&H);
    lo = *reinterpret_cast<uint32_t*>(&L);
}

// ---------------- HMMA split-bf16 GEMM: C[M,Ntot] = A@B^T (+bias) ------------
#define MM_THREADS 256
#define SM_AH 0
#define SM_AL 16384
#define SM_BH 32768
#define SM_BL 49152
#define BUF_BYTES 65536
#define SM_TOTAL (2*BUF_BYTES)            // 131072

__global__ __launch_bounds__(MM_THREADS)
void mm_bf16_kernel(const __nv_bfloat16* __restrict__ Ah,
                    const __nv_bfloat16* __restrict__ Al,
                    const __nv_bfloat16* __restrict__ Bh,
                    const __nv_bfloat16* __restrict__ Bl,
                    const float* __restrict__ bias,
                    float* __restrict__ C,
                    int Ntot, int K)
{
    extern __shared__ __align__(1024) char smem[];
    const uint32_t sb = smem_u32(smem);
    const int tid  = threadIdx.x;
    const int wid  = tid >> 5;
    const int lane = tid & 31;
    const int m0 = blockIdx.y * 128;
    const int n0 = blockIdx.x * 128;
    const int wm = wid >> 2;
    const int wn = wid & 3;

    const int a_row = (lane & 7) | (((lane >> 3) & 1) << 3);
    const int a_kb  = (lane >> 4) * 16;
    const int b_row = (lane & 7) | ((lane >> 4) << 3);
    const int b_kb  = ((lane >> 3) & 1) * 16;

    const int cr = tid >> 3;
    const int cc = tid & 7;
    const uint32_t so_base = (uint32_t)(cr * 128 + cc * 16);

    float acc[4][4][4] = {};

    const int NT = K / 64;

    auto issue_tile = [&](int t) {
        const int k0 = t * 64;
        const uint32_t bb = (uint32_t)(t & 1) * BUF_BYTES;
#pragma unroll
        for (int i = 0; i < 4; i++) {
            const int r = cr + i * 32;
            const uint32_t so = sw128(so_base + (uint32_t)i * 32 * 128);
            const size_t aoff = (size_t)(m0 + r) * K + k0 + cc * 8;
            const size_t boff = (size_t)(n0 + r) * K + k0 + cc * 8;
            cpasync16(sb + bb + SM_AH + so, Ah + aoff);
            cpasync16(sb + bb + SM_AL + so, Al + aoff);
            cpasync16(sb + bb + SM_BH + so, Bh + boff);
            cpasync16(sb + bb + SM_BL + so, Bl + boff);
        }
        CP_COMMIT();
    };

    issue_tile(0);

    for (int t = 0; t < NT; t++) {
        if (t + 1 < NT) {
            issue_tile(t + 1);
            CP_WAIT(1);
        } else {
            CP_WAIT(0);
        }
        __syncthreads();

        const uint32_t bb = (uint32_t)(t & 1) * BUF_BYTES;

#pragma unroll
        for (int k16 = 0; k16 < 4; k16++) {
            const int kb2 = k16 * 32;

            uint32_t bh[4][2], bl[4][2], af[4][4];
#pragma unroll
            for (int g = 0; g < 2; g++) {
                const uint32_t off =
                    sw128((uint32_t)((wn * 32 + g * 16 + b_row) * 128 + kb2 + b_kb));
                uint32_t r[4];
                ldsm4(r, sb + bb + SM_BH + off);
                bh[g*2][0] = r[0]; bh[g*2][1] = r[1];
                bh[g*2+1][0] = r[2]; bh[g*2+1][1] = r[3];
                ldsm4(r, sb + bb + SM_BL + off);
                bl[g*2][0] = r[0]; bl[g*2][1] = r[1];
                bl[g*2+1][0] = r[2]; bl[g*2+1][1] = r[3];
            }
#pragma unroll
            for (int mi = 0; mi < 4; mi++) {
                const uint32_t off =
                    sw128((uint32_t)((wm * 64 + mi * 16 + a_row) * 128 + kb2 + a_kb));
                ldsm4(af[mi], sb + bb + SM_AH + off);
            }
#pragma unroll
            for (int mi = 0; mi < 4; mi++)
#pragma unroll
                for (int ni = 0; ni < 4; ni++) {
                    mma_bf16(acc[mi][ni], af[mi], bh[ni]);
                    mma_bf16(acc[mi][ni], af[mi], bl[ni]);
                }
#pragma unroll
            for (int mi = 0; mi < 4; mi++) {
                const uint32_t off =
                    sw128((uint32_t)((wm * 64 + mi * 16 + a_row) * 128 + kb2 + a_kb));
                ldsm4(af[mi], sb + bb + SM_AL + off);
            }
#pragma unroll
            for (int mi = 0; mi < 4; mi++)
#pragma unroll
                for (int ni = 0; ni < 4; ni++)
                    mma_bf16(acc[mi][ni], af[mi], bh[ni]);
        }
        __syncthreads();
    }

    const int g   = lane >> 2;
    const int tig = lane & 3;
#pragma unroll
    for (int mi = 0; mi < 4; mi++) {
#pragma unroll
        for (int ni = 0; ni < 4; ni++) {
            const int row = m0 + wm * 64 + mi * 16 + g;
            const int col = n0 + wn * 32 + ni * 8 + tig * 2;
            float2 v0, v1;
            v0.x = acc[mi][ni][0]; v0.y = acc[mi][ni][1];
            v1.x = acc[mi][ni][2]; v1.y = acc[mi][ni][3];
            if (bias) {
                const float b0 = bias[col], b1 = bias[col + 1];
                v0.x += b0; v0.y += b1;
                v1.x += b0; v1.y += b1;
            }
            *(float2*)(C + (size_t)row * Ntot + col)       = v0;
            *(float2*)(C + (size_t)(row + 8) * Ntot + col) = v1;
        }
    }
}

// ---------------- fp32 -> bf16 hi/lo split ------------------------------------
__global__ void split_kernel(const float* __restrict__ in,
                             __nv_bfloat16* __restrict__ hi,
                             __nv_bfloat16* __restrict__ lo, int n4)
{
    int i = blockIdx.x * blockDim.x + threadIdx.x;
    if (i >= n4) return;
    float4 v = ((const float4*)in)[i];
    __nv_bfloat162 H0, H1, L0, L1;
    split_bf16(v.x, H0.x, L0.x);
    split_bf16(v.y, H0.y, L0.y);
    split_bf16(v.z, H1.x, L1.x);
    split_bf16(v.w, H1.y, L1.y);
    ((__nv_bfloat162*)hi)[i * 2 + 0] = H0;
    ((__nv_bfloat162*)hi)[i * 2 + 1] = H1;
    ((__nv_bfloat162*)lo)[i * 2 + 0] = L0;
    ((__nv_bfloat162*)lo)[i * 2 + 1] = L1;
}

// ---------------- fp32 [K,N] -> bf16 hi/lo transposed [N,K] ------------------
__global__ void transpose_split_kernel(const float* __restrict__ W,
                                       __nv_bfloat16* __restrict__ Th,
                                       __nv_bfloat16* __restrict__ Tl,
                                       int K, int N)
{
    __shared__ float tile[32][33];
    const int n0 = blockIdx.x * 32;
    const int k0 = blockIdx.y * 32;
    const int tx = threadIdx.x;
    const int ty = threadIdx.y;
#pragma unroll
    for (int i = 0; i < 4; i++) {
        int k = k0 + ty + i * 8;
        tile[ty + i * 8][tx] = W[(size_t)k * N + n0 + tx];
    }
    __syncthreads();
#pragma unroll
    for (int i = 0; i < 4; i++) {
        int n = n0 + ty + i * 8;
        float v = tile[tx][ty + i * 8];
        __nv_bfloat16 h, l;
        split_bf16(v, h, l);
        Th[(size_t)n * K + k0 + tx] = h;
        Tl[(size_t)n * K + k0 + tx] = l;
    }
}

// ---------------- RoPE + scatter into split bf16 attention operands ----------
// All outputs [BH, T, D]; every store is a coalesced bf16x2.
__global__ void rope_scatter_kernel()
{
    int idx = blockIdx.x * blockDim.x + threadIdx.x;
    const int TOT = MTOT * 3 * HH * (DD / 2);
    if (idx >= TOT) return;

    int row = idx / 1536;            // b*T + t
    int c0  = idx % 1536;
    int sel = c0 / 512;              // 0=q 1=k 2=v
    int h   = (c0 % 512) / 32;
    int p   = c0 % 32;               // pair index (d = 2p, 2p+1)
    int t   = row % TT;
    int b   = row / TT;
    int bh  = b * HH + h;

    size_t src = (size_t)row * QKVN + sel * CC + h * DD + 2 * p;
    float x0 = g_qkv[src];
    float x1 = g_qkv[src + 1];

    size_t o = ((size_t)bh * TT + t) * DD + 2 * p;

    if (sel == 2) {
        __nv_bfloat162 H, L;
        split_bf16(x0, H.x, L.x);
        split_bf16(x1, H.y, L.y);
        *(__nv_bfloat162*)(g_vh + o) = H;
        *(__nv_bfloat162*)(g_vl + o) = L;
        return;
    }

    const float LN1E4_OVER_32 = 0.28782313662425572f;
    float inv_freq = __expf(-(float)p * LN1E4_OVER_32);
    float ang = (float)t * inv_freq;
    float s, c;
    sincosf(ang, &s, &c);
    float r0 = x0 * c - x1 * s;
    float r1 = x1 * c + x0 * s;

    if (sel == 0) {
        r0 *= 0.125f; r1 *= 0.125f;     // fold in D^-0.5
        __nv_bfloat162 H, L;
        split_bf16(r0, H.x, L.x);
        split_bf16(r1, H.y, L.y);
        *(__nv_bfloat162*)(g_qh + o) = H;
        *(__nv_bfloat162*)(g_ql + o) = L;
    } else {
        __nv_bfloat162 H, L;
        split_bf16(r0, H.x, L.x);
        split_bf16(r1, H.y, L.y);
        *(__nv_bfloat162*)(g_kh + o) = H;
        *(__nv_bfloat162*)(g_kl + o) = L;
    }
}

// ---------------- flash attention on HMMA (split bf16, causal) ----------------
// CTA: 128 queries x 1 head. 8 warps, warp = 16 query rows (m16).
// K and V both staged as [key, d] tiles; V fragments built via ldmatrix.trans.
#define FA_THREADS 256
#define FQ_H 0
#define FQ_L 16384
#define FKV  32768
#define FK_H 0
#define FK_L 8192
#define FV_H 16384
#define FV_L 24576
#define FA_BUF 32768
#define FA_SMEM (FKV + 2*FA_BUF)          // 98304

__global__ __launch_bounds__(FA_THREADS)
void attn_mma_kernel()
{
    extern __shared__ __align__(1024) char smem[];
    const uint32_t sb = smem_u32(smem);
    const int tid  = threadIdx.x;
    const int wid  = tid >> 5;
    const int lane = tid & 31;
    const int bh = blockIdx.y;
    const int qb = (int)gridDim.x - 1 - (int)blockIdx.x;   // heavy tiles first
    const int q0 = qb * 128;
    const int g   = lane >> 2;
    const int tig = lane & 3;

    const int a_row = (lane & 7) | (((lane >> 3) & 1) << 3);
    const int a_kb  = (lane >> 4) * 16;
    const int b_row = (lane & 7) | ((lane >> 4) << 3);
    const int b_kb  = ((lane >> 3) & 1) * 16;
    // V-trans fragment mapping (ldmatrix.trans from [key][d] tile)
    const int vt_row = lane & 15;          // key row within k16 step
    const int vt_cb  = (lane >> 4) * 16;   // d byte offset (d + 8 group)

    const __nv_bfloat16* Qh = g_qh + (size_t)bh * TT * DD;
    const __nv_bfloat16* Ql = g_ql + (size_t)bh * TT * DD;
    const __nv_bfloat16* Kh = g_kh + (size_t)bh * TT * DD;
    const __nv_bfloat16* Kl = g_kl + (size_t)bh * TT * DD;
    const __nv_bfloat16* Vh = g_vh + (size_t)bh * TT * DD;
    const __nv_bfloat16* Vl = g_vl + (size_t)bh * TT * DD;

    const int cr = tid >> 3;              // 0..31
    const int cc = tid & 7;

    // stage Q tile (128 x 64, hi/lo) — grouped with key-tile 0
    {
#pragma unroll
        for (int i = 0; i < 4; i++) {
            const int r = cr + i * 32;
            const uint32_t so = sw128((uint32_t)(r * 128 + cc * 16));
            const size_t off = (size_t)(q0 + r) * DD + cc * 8;
            cpasync16(sb + FQ_H + so, Qh + off);
            cpasync16(sb + FQ_L + so, Ql + off);
        }
    }

    auto issue_tile = [&](int t) {
        const int jt = t * 64;
        const uint32_t bb = sb + FKV + (uint32_t)(t & 1) * FA_BUF;
#pragma unroll
        for (int i = 0; i < 2; i++) {
            const int r = cr + i * 32;    // 0..63
            const uint32_t so = sw128((uint32_t)(r * 128 + cc * 16));
            const size_t off = (size_t)(jt + r) * DD + cc * 8;
            cpasync16(bb + FK_H + so, Kh + off);
            cpasync16(bb + FK_L + so, Kl + off);
            cpasync16(bb + FV_H + so, Vh + off);
            cpasync16(bb + FV_L + so, Vl + off);
        }
        CP_COMMIT();
    };

    issue_tile(0);

    const int NTL = qb * 2 + 2;           // key tiles to process
    const int wqmin = q0 + wid * 16;
    const int wqmax = wqmin + 15;
    const int r0 = wqmin + g;
    const int r1 = r0 + 8;

    float o[8][4] = {};
    float m0 = -1e30f, m1 = -1e30f, l0 = 0.0f, l1 = 0.0f;
    uint32_t qfh[4][4], qfl[4][4];

    for (int t = 0; t < NTL; t++) {
        if (t + 1 < NTL) {
            issue_tile(t + 1);
            CP_WAIT(1);
        } else {
            CP_WAIT(0);
        }
        __syncthreads();

        if (t == 0) {
#pragma unroll
            for (int k16 = 0; k16 < 4; k16++) {
                const uint32_t off =
                    sw128((uint32_t)((wid * 16 + a_row) * 128 + k16 * 32 + a_kb));
                ldsm4(qfh[k16], sb + FQ_H + off);
                ldsm4(qfl[k16], sb + FQ_L + off);
            }
        }

        const int jt = t * 64;
        if (jt <= wqmax) {
            const uint32_t bb = sb + FKV + (uint32_t)(t & 1) * FA_BUF;

            // ---- S = Q K^T (split) ----
            float s[8][4] = {};
#pragma unroll
            for (int g2 = 0; g2 < 4; g2++) {
#pragma unroll
                for (int k16 = 0; k16 < 4; k16++) {
                    const uint32_t off =
                        sw128((uint32_t)((g2 * 16 + b_row) * 128 + k16 * 32 + b_kb));
                    uint32_t rbh[4], rbl[4];
                    ldsm4(rbh, bb + FK_H + off);
                    ldsm4(rbl, bb + FK_L + off);
                    mma_bf16(s[g2*2],   qfh[k16], rbh);
                    mma_bf16(s[g2*2+1], qfh[k16], rbh + 2);
                    mma_bf16(s[g2*2],   qfh[k16], rbl);
                    mma_bf16(s[g2*2+1], qfh[k16], rbl + 2);
                    mma_bf16(s[g2*2],   qfl[k16], rbh);
                    mma_bf16(s[g2*2+1], qfl[k16], rbh + 2);
                }
            }

            // ---- causal mask ----
            if (jt + 63 > wqmin) {
#pragma unroll
                for (int st = 0; st < 8; st++) {
                    const int k = jt + st * 8 + tig * 2;
                    if (k     > r0) s[st][0] = -1e30f;
                    if (k + 1 > r0) s[st][1] = -1e30f;
                    if (k     > r1) s[st][2] = -1e30f;
                    if (k + 1 > r1) s[st][3] = -1e30f;
                }
            }

            // ---- online softmax ----
            float mx0 = -1e30f, mx1 = -1e30f;
#pragma unroll
            for (int st = 0; st < 8; st++) {
                mx0 = fmaxf(mx0, fmaxf(s[st][0], s[st][1]));
                mx1 = fmaxf(mx1, fmaxf(s[st][2], s[st][3]));
            }
            mx0 = fmaxf(mx0, __shfl_xor_sync(0xffffffffu, mx0, 1));
            mx0 = fmaxf(mx0, __shfl_xor_sync(0xffffffffu, mx0, 2));
            mx1 = fmaxf(mx1, __shfl_xor_sync(0xffffffffu, mx1, 1));
            mx1 = fmaxf(mx1, __shfl_xor_sync(0xffffffffu, mx1, 2));

            const float mt0 = fmaxf(m0, mx0);
            const float mt1 = fmaxf(m1, mx1);
            const float rs0 = __expf(m0 - mt0);
            const float rs1 = __expf(m1 - mt1);
            l0 *= rs0; l1 *= rs1;
            m0 = mt0;  m1 = mt1;
#pragma unroll
            for (int st = 0; st < 8; st++) {
                o[st][0] *= rs0; o[st][1] *= rs0;
                o[st][2] *= rs1; o[st][3] *= rs1;
            }

            float ps0 = 0.0f, ps1 = 0.0f;
#pragma unroll
            for (int st = 0; st < 8; st++) {
                s[st][0] = __expf(s[st][0] - m0);
                s[st][1] = __expf(s[st][1] - m0);
                s[st][2] = __expf(s[st][2] - m1);
                s[st][3] = __expf(s[st][3] - m1);
                ps0 += s[st][0] + s[st][1];
                ps1 += s[st][2] + s[st][3];
            }
            ps0 += __shfl_xor_sync(0xffffffffu, ps0, 1);
            ps0 += __shfl_xor_sync(0xffffffffu, ps0, 2);
            ps1 += __shfl_xor_sync(0xffffffffu, ps1, 1);
            ps1 += __shfl_xor_sync(0xffffffffu, ps1, 2);
            l0 += ps0; l1 += ps1;

            // ---- O += P V (split); V fragments via ldmatrix.trans ----
#pragma unroll
            for (int k16 = 0; k16 < 4; k16++) {
                uint32_t ah[4], al[4];
                pack_split2(s[2*k16][0],   s[2*k16][1],   ah[0], al[0]);
                pack_split2(s[2*k16][2],   s[2*k16][3],   ah[1], al[1]);
                pack_split2(s[2*k16+1][0], s[2*k16+1][1], ah[2], al[2]);
                pack_split2(s[2*k16+1][2], s[2*k16+1][3], ah[3], al[3]);
#pragma unroll
                for (int g2 = 0; g2 < 4; g2++) {
                    const uint32_t off =
                        sw128((uint32_t)((k16 * 16 + vt_row) * 128 + g2 * 32 + vt_cb));
                    uint32_t vbh[4], vbl[4];
                    ldsm4t(vbh, bb + FV_H + off);
                    ldsm4t(vbl, bb + FV_L + off);
                    mma_bf16(o[g2*2],   ah, vbh);
                    mma_bf16(o[g2*2+1], ah, vbh + 2);
                    mma_bf16(o[g2*2],   ah, vbl);
                    mma_bf16(o[g2*2+1], ah, vbl + 2);
                    mma_bf16(o[g2*2],   al, vbh);
                    mma_bf16(o[g2*2+1], al, vbh + 2);
                }
            }
        }
        __syncthreads();
    }

    // ---- epilogue: write split bf16 att output [B, T, C] ----
    const int b = bh >> 4;
    const int h = bh & 15;
    const float inv0 = 1.0f / l0;
    const float inv1 = 1.0f / l1;
    const size_t row0 = ((size_t)(b * TT + r0)) * CC + h * DD;
    const size_t row1 = ((size_t)(b * TT + r1)) * CC + h * DD;
#pragma unroll
    for (int st = 0; st < 8; st++) {
        const int col = st * 8 + tig * 2;
        uint32_t hi0, lo0, hi1, lo1;
        pack_split2(o[st][0] * inv0, o[st][1] * inv0, hi0, lo0);
        pack_split2(o[st][2] * inv1, o[st][3] * inv1, hi1, lo1);
        *(uint32_t*)(g_ath + row0 + col) = hi0;
        *(uint32_t*)(g_atl + row0 + col) = lo0;
        *(uint32_t*)(g_ath + row1 + col) = hi1;
        *(uint32_t*)(g_atl + row1 + col) = lo1;
    }
}

// ---------------- launch ------------------------------------------------------
extern "C" void kernel_launch(void* const* d_in, const int* in_sizes, int n_in,
                              void* d_out, int out_size)
{
    const float* x    = (const float*)d_in[0];
    const float* Wqkv = (const float*)d_in[1];
    const float* Wo   = (const float*)d_in[2];
    const float* bo   = (const float*)d_in[3];
    float* out = (float*)d_out;

    (void)in_sizes; (void)n_in; (void)out_size;

    static int smem_set = 0;
    if (!smem_set) {
        cudaFuncSetAttribute(mm_bf16_kernel,
                             cudaFuncAttributeMaxDynamicSharedMemorySize, SM_TOTAL);
        cudaFuncSetAttribute(attn_mma_kernel,
                             cudaFuncAttributeMaxDynamicSharedMemorySize, FA_SMEM);
        smem_set = 1;
    }

    __nv_bfloat16 *xh, *xl, *wqh, *wql, *ath, *atl, *woh, *wol;
    cudaGetSymbolAddress((void**)&xh,  g_xh);
    cudaGetSymbolAddress((void**)&xl,  g_xl);
    cudaGetSymbolAddress((void**)&wqh, g_wqkvTh);
    cudaGetSymbolAddress((void**)&wql, g_wqkvTl);
    cudaGetSymbolAddress((void**)&ath, g_ath);
    cudaGetSymbolAddress((void**)&atl, g_atl);
    cudaGetSymbolAddress((void**)&woh, g_woTh);
    cudaGetSymbolAddress((void**)&wol, g_woTl);
    float* qkvp;
    cudaGetSymbolAddress((void**)&qkvp, g_qkv);

    // 1) split x to bf16 hi/lo
    {
        int n4 = MTOT * CC / 4;
        split_kernel<<<(n4 + 255) / 256, 256>>>(x, xh, xl, n4);
    }
    // 2) transpose+split Wqkv -> [3072,1024]
    {
        dim3 grid(QKVN / 32, CC / 32);
        transpose_split_kernel<<<grid, dim3(32, 8)>>>(Wqkv, wqh, wql, CC, QKVN);
    }
    // 3) QKV GEMM (HMMA)
    {
        dim3 grid(QKVN / 128, MTOT / 128);
        mm_bf16_kernel<<<grid, MM_THREADS, SM_TOTAL>>>(
            xh, xl, wqh, wql, nullptr, qkvp, QKVN, CC);
    }
    // 4) RoPE + scatter into split attention operands (all coalesced)
    {
        int tot = MTOT * 3 * HH * (DD / 2);
        rope_scatter_kernel<<<(tot + 255) / 256, 256>>>();
    }
    // 5) causal flash attention on tensor cores
    {
        dim3 grid(TT / 128, BB * HH);
        attn_mma_kernel<<<grid, FA_THREADS, FA_SMEM>>>();
    }
    // 6) transpose+split Wo
    {
        dim3 grid(CC / 32, CC / 32);
        transpose_split_kernel<<<grid, dim3(32, 8)>>>(Wo, woh, wol, CC, CC);
    }
    // 7) output projection (HMMA) + bias
    {
        dim3 grid(CC / 128, MTOT / 128);
        mm_bf16_kernel<<<grid, MM_THREADS, SM_TOTAL>>>(
            ath, atl, woh, wol, bo, out, CC, CC);
    }
}

// round 10
// speedup vs baseline: 3.8219x; 1.0210x over previous
#include <cuda_runtime.h>
#include <cuda_bf16.h>
#include <math.h>
#include <stdint.h>

// Problem constants
#define BB   2
#define TT   2048
#define CC   1024
#define HH   16
#define DD   64
#define MTOT (BB*TT)          // 4096
#define QKVN (3*CC)           // 3072

// ---------------- scratch (device globals; no allocs allowed) ----------------
// bf16 split operands
__device__ __nv_bfloat16 g_xh[(size_t)MTOT * CC];       // x hi
__device__ __nv_bfloat16 g_xl[(size_t)MTOT * CC];       // x lo
__device__ __nv_bfloat16 g_wqkvTh[(size_t)QKVN * CC];   // Wqkv^T hi  [N,K]
__device__ __nv_bfloat16 g_wqkvTl[(size_t)QKVN * CC];
__device__ __nv_bfloat16 g_ath[(size_t)MTOT * CC];      // attention out hi
__device__ __nv_bfloat16 g_atl[(size_t)MTOT * CC];      // attention out lo
__device__ __nv_bfloat16 g_woTh[(size_t)CC * CC];       // Wo^T hi    [N,K]
__device__ __nv_bfloat16 g_woTl[(size_t)CC * CC];

// attention operands, hi/lo split — ALL in [BH, T, D] layout
__device__ __nv_bfloat16 g_qh[(size_t)BB*HH*TT*DD];     // (scaled by D^-0.5)
__device__ __nv_bfloat16 g_ql[(size_t)BB*HH*TT*DD];
__device__ __nv_bfloat16 g_kh[(size_t)BB*HH*TT*DD];
__device__ __nv_bfloat16 g_kl[(size_t)BB*HH*TT*DD];
__device__ __nv_bfloat16 g_vh[(size_t)BB*HH*TT*DD];
__device__ __nv_bfloat16 g_vl[(size_t)BB*HH*TT*DD];

// ---------------- helpers -----------------------------------------------------
__device__ __forceinline__ uint32_t smem_u32(const void* p) {
    uint32_t a;
    asm("{ .reg .u64 t; cvta.to.shared.u64 t, %1; cvt.u32.u64 %0, t; }"
        : "=r"(a) : "l"(p));
    return a;
}
__device__ __forceinline__ uint32_t sw128(uint32_t b) { return b ^ ((b >> 3) & 0x70); }

__device__ __forceinline__ void ldsm4(uint32_t* r, uint32_t addr) {
    asm volatile("ldmatrix.sync.aligned.m8n8.x4.shared.b16 {%0,%1,%2,%3}, [%4];"
                 : "=r"(r[0]), "=r"(r[1]), "=r"(r[2]), "=r"(r[3]) : "r"(addr));
}
__device__ __forceinline__ void ldsm4t(uint32_t* r, uint32_t addr) {
    asm volatile("ldmatrix.sync.aligned.m8n8.x4.trans.shared.b16 {%0,%1,%2,%3}, [%4];"
                 : "=r"(r[0]), "=r"(r[1]), "=r"(r[2]), "=r"(r[3]) : "r"(addr));
}
__device__ __forceinline__ void mma_bf16(float* c, const uint32_t* a, const uint32_t* b) {
    asm volatile(
        "mma.sync.aligned.m16n8k16.row.col.f32.bf16.bf16.f32 "
        "{%0,%1,%2,%3}, {%4,%5,%6,%7}, {%8,%9}, {%0,%1,%2,%3};"
        : "+f"(c[0]), "+f"(c[1]), "+f"(c[2]), "+f"(c[3])
        : "r"(a[0]), "r"(a[1]), "r"(a[2]), "r"(a[3]), "r"(b[0]), "r"(b[1]));
}
__device__ __forceinline__ void cpasync16(uint32_t dst, const void* src) {
    asm volatile("cp.async.cg.shared.global [%0], [%1], 16;"
                 :: "r"(dst), "l"(src) : "memory");
}
#define CP_COMMIT() asm volatile("cp.async.commit_group;" ::: "memory")
#define CP_WAIT(n)  asm volatile("cp.async.wait_group %0;" :: "n"(n) : "memory")

__device__ __forceinline__ void split_bf16(float v, __nv_bfloat16& h, __nv_bfloat16& l) {
    h = __float2bfloat16(v);
    l = __float2bfloat16(v - __bfloat162float(h));
}
__device__ __forceinline__ void pack_split2(float x, float y, uint32_t& hi, uint32_t& lo) {
    __nv_bfloat162 H, L;
    H.x = __float2bfloat16(x);
    H.y = __float2bfloat16(y);
    L.x = __float2bfloat16(x - __bfloat162float(H.x));
    L.y = __float2bfloat16(y - __bfloat162float(H.y));
    hi = *reinterpret_cast<uint32_t*>(&H);
    lo = *reinterpret_cast<uint32_t*>(&L);
}

// ---------------- HMMA split-bf16 GEMM mainloop (shared) ----------------------
#define MM_THREADS 256
#define SM_AH 0
#define SM_AL 16384
#define SM_BH 32768
#define SM_BL 49152
#define BUF_BYTES 65536
#define SM_TOTAL (2*BUF_BYTES)            // 131072

__device__ __forceinline__ void mm_mainloop(
    const __nv_bfloat16* __restrict__ Ah, const __nv_bfloat16* __restrict__ Al,
    const __nv_bfloat16* __restrict__ Bh, const __nv_bfloat16* __restrict__ Bl,
    char* smem, uint32_t sb, int m0, int n0, int K,
    int tid, int wid, int lane, float acc[4][4][4])
{
    const int wm = wid >> 2;
    const int wn = wid & 3;
    const int a_row = (lane & 7) | (((lane >> 3) & 1) << 3);
    const int a_kb  = (lane >> 4) * 16;
    const int b_row = (lane & 7) | ((lane >> 4) << 3);
    const int b_kb  = ((lane >> 3) & 1) * 16;

    const int cr = tid >> 3;
    const int cc = tid & 7;
    const uint32_t so_base = (uint32_t)(cr * 128 + cc * 16);

    const int NT = K / 64;

    auto issue_tile = [&](int t) {
        const int k0 = t * 64;
        const uint32_t bb = (uint32_t)(t & 1) * BUF_BYTES;
#pragma unroll
        for (int i = 0; i < 4; i++) {
            const int r = cr + i * 32;
            const uint32_t so = sw128(so_base + (uint32_t)i * 32 * 128);
            const size_t aoff = (size_t)(m0 + r) * K + k0 + cc * 8;
            const size_t boff = (size_t)(n0 + r) * K + k0 + cc * 8;
            cpasync16(sb + bb + SM_AH + so, Ah + aoff);
            cpasync16(sb + bb + SM_AL + so, Al + aoff);
            cpasync16(sb + bb + SM_BH + so, Bh + boff);
            cpasync16(sb + bb + SM_BL + so, Bl + boff);
        }
        CP_COMMIT();
    };

    issue_tile(0);

    for (int t = 0; t < NT; t++) {
        if (t + 1 < NT) {
            issue_tile(t + 1);
            CP_WAIT(1);
        } else {
            CP_WAIT(0);
        }
        __syncthreads();

        const uint32_t bb = (uint32_t)(t & 1) * BUF_BYTES;

#pragma unroll
        for (int k16 = 0; k16 < 4; k16++) {
            const int kb2 = k16 * 32;

            uint32_t bhf[4][2], blf[4][2], af[4][4];
#pragma unroll
            for (int g = 0; g < 2; g++) {
                const uint32_t off =
                    sw128((uint32_t)((wn * 32 + g * 16 + b_row) * 128 + kb2 + b_kb));
                uint32_t r[4];
                ldsm4(r, sb + bb + SM_BH + off);
                bhf[g*2][0] = r[0]; bhf[g*2][1] = r[1];
                bhf[g*2+1][0] = r[2]; bhf[g*2+1][1] = r[3];
                ldsm4(r, sb + bb + SM_BL + off);
                blf[g*2][0] = r[0]; blf[g*2][1] = r[1];
                blf[g*2+1][0] = r[2]; blf[g*2+1][1] = r[3];
            }
#pragma unroll
            for (int mi = 0; mi < 4; mi++) {
                const uint32_t off =
                    sw128((uint32_t)((wm * 64 + mi * 16 + a_row) * 128 + kb2 + a_kb));
                ldsm4(af[mi], sb + bb + SM_AH + off);
            }
#pragma unroll
            for (int mi = 0; mi < 4; mi++)
#pragma unroll
                for (int ni = 0; ni < 4; ni++) {
                    mma_bf16(acc[mi][ni], af[mi], bhf[ni]);
                    mma_bf16(acc[mi][ni], af[mi], blf[ni]);
                }
#pragma unroll
            for (int mi = 0; mi < 4; mi++) {
                const uint32_t off =
                    sw128((uint32_t)((wm * 64 + mi * 16 + a_row) * 128 + kb2 + a_kb));
                ldsm4(af[mi], sb + bb + SM_AL + off);
            }
#pragma unroll
            for (int mi = 0; mi < 4; mi++)
#pragma unroll
                for (int ni = 0; ni < 4; ni++)
                    mma_bf16(acc[mi][ni], af[mi], bhf[ni]);
        }
        __syncthreads();
    }
}

// ---------------- GEMM kernel: plain epilogue OR fused RoPE+split ------------
// fuse_rope==0: C[M,Ntot] = A@B^T (+bias), fp32 out.
// fuse_rope==1: QKV epilogue — applies RoPE to q/k, splits to bf16 hi/lo,
//               scatters into g_qh/ql, g_kh/kl, g_vh/vl ([BH,T,D]).
__global__ __launch_bounds__(MM_THREADS)
void mm_bf16_kernel(const __nv_bfloat16* __restrict__ Ah,
                    const __nv_bfloat16* __restrict__ Al,
                    const __nv_bfloat16* __restrict__ Bh,
                    const __nv_bfloat16* __restrict__ Bl,
                    const float* __restrict__ bias,
                    float* __restrict__ C,
                    int Ntot, int K, int fuse_rope)
{
    extern __shared__ __align__(1024) char smem[];
    const uint32_t sb = smem_u32(smem);
    const int tid  = threadIdx.x;
    const int wid  = tid >> 5;
    const int lane = tid & 31;
    const int m0 = blockIdx.y * 128;
    const int n0 = blockIdx.x * 128;

    float acc[4][4][4] = {};
    mm_mainloop(Ah, Al, Bh, Bl, smem, sb, m0, n0, K, tid, wid, lane, acc);

    const int wm = wid >> 2;
    const int wn = wid & 3;
    const int g   = lane >> 2;
    const int tig = lane & 3;

    if (!fuse_rope) {
#pragma unroll
        for (int mi = 0; mi < 4; mi++) {
#pragma unroll
            for (int ni = 0; ni < 4; ni++) {
                const int row = m0 + wm * 64 + mi * 16 + g;
                const int col = n0 + wn * 32 + ni * 8 + tig * 2;
                float2 v0, v1;
                v0.x = acc[mi][ni][0]; v0.y = acc[mi][ni][1];
                v1.x = acc[mi][ni][2]; v1.y = acc[mi][ni][3];
                if (bias) {
                    const float b0 = bias[col], b1 = bias[col + 1];
                    v0.x += b0; v0.y += b1;
                    v1.x += b0; v1.y += b1;
                }
                *(float2*)(C + (size_t)row * Ntot + col)       = v0;
                *(float2*)(C + (size_t)(row + 8) * Ntot + col) = v1;
            }
        }
        return;
    }

    // ---- fused RoPE + split epilogue (sel uniform per CTA: 1024 % 128 == 0) --
    const int sel = n0 >> 10;             // 0=q 1=k 2=v
    const float LN1E4_OVER_32 = 0.28782313662425572f;

#pragma unroll
    for (int ni = 0; ni < 4; ni++) {
        const int col = n0 + wn * 32 + ni * 8 + tig * 2;   // even
        const int hc  = (col & 1023) >> 6;
        const int d   = col & 63;
        const int p   = d >> 1;
        float inv_freq = 0.0f;
        if (sel < 2) inv_freq = __expf(-(float)p * LN1E4_OVER_32);

#pragma unroll
        for (int mi = 0; mi < 4; mi++) {
#pragma unroll
            for (int half = 0; half < 2; half++) {
                const int row = m0 + wm * 64 + mi * 16 + g + half * 8;
                const int t   = row & (TT - 1);
                const int b   = row >> 11;
                const size_t o = (((size_t)(b * HH + hc)) * TT + t) * DD + d;
                float v0 = acc[mi][ni][half * 2 + 0];
                float v1 = acc[mi][ni][half * 2 + 1];

                if (sel < 2) {
                    float sn, cs;
                    sincosf((float)t * inv_freq, &sn, &cs);
                    float r0 = v0 * cs - v1 * sn;
                    float r1 = v1 * cs + v0 * sn;
                    if (sel == 0) { r0 *= 0.125f; r1 *= 0.125f; }
                    uint32_t hi, lo;
                    pack_split2(r0, r1, hi, lo);
                    if (sel == 0) {
                        *(uint32_t*)(g_qh + o) = hi;
                        *(uint32_t*)(g_ql + o) = lo;
                    } else {
                        *(uint32_t*)(g_kh + o) = hi;
                        *(uint32_t*)(g_kl + o) = lo;
                    }
                } else {
                    uint32_t hi, lo;
                    pack_split2(v0, v1, hi, lo);
                    *(uint32_t*)(g_vh + o) = hi;
                    *(uint32_t*)(g_vl + o) = lo;
                }
            }
        }
    }
}

// ---------------- fp32 -> bf16 hi/lo split ------------------------------------
__global__ void split_kernel(const float* __restrict__ in,
                             __nv_bfloat16* __restrict__ hi,
                             __nv_bfloat16* __restrict__ lo, int n4)
{
    int i = blockIdx.x * blockDim.x + threadIdx.x;
    if (i >= n4) return;
    float4 v = ((const float4*)in)[i];
    __nv_bfloat162 H0, H1, L0, L1;
    split_bf16(v.x, H0.x, L0.x);
    split_bf16(v.y, H0.y, L0.y);
    split_bf16(v.z, H1.x, L1.x);
    split_bf16(v.w, H1.y, L1.y);
    ((__nv_bfloat162*)hi)[i * 2 + 0] = H0;
    ((__nv_bfloat162*)hi)[i * 2 + 1] = H1;
    ((__nv_bfloat162*)lo)[i * 2 + 0] = L0;
    ((__nv_bfloat162*)lo)[i * 2 + 1] = L1;
}

// ---------------- fp32 [K,N] -> bf16 hi/lo transposed [N,K] ------------------
__global__ void transpose_split_kernel(const float* __restrict__ W,
                                       __nv_bfloat16* __restrict__ Th,
                                       __nv_bfloat16* __restrict__ Tl,
                                       int K, int N)
{
    __shared__ float tile[32][33];
    const int n0 = blockIdx.x * 32;
    const int k0 = blockIdx.y * 32;
    const int tx = threadIdx.x;
    const int ty = threadIdx.y;
#pragma unroll
    for (int i = 0; i < 4; i++) {
        int k = k0 + ty + i * 8;
        tile[ty + i * 8][tx] = W[(size_t)k * N + n0 + tx];
    }
    __syncthreads();
#pragma unroll
    for (int i = 0; i < 4; i++) {
        int n = n0 + ty + i * 8;
        float v = tile[tx][ty + i * 8];
        __nv_bfloat16 h, l;
        split_bf16(v, h, l);
        Th[(size_t)n * K + k0 + tx] = h;
        Tl[(size_t)n * K + k0 + tx] = l;
    }
}

// ---------------- flash attention on HMMA (split bf16, causal) ----------------
#define FA_THREADS 256
#define FQ_H 0
#define FQ_L 16384
#define FKV  32768
#define FK_H 0
#define FK_L 8192
#define FV_H 16384
#define FV_L 24576
#define FA_BUF 32768
#define FA_SMEM (FKV + 2*FA_BUF)          // 98304

__global__ __launch_bounds__(FA_THREADS)
void attn_mma_kernel()
{
    extern __shared__ __align__(1024) char smem[];
    const uint32_t sb = smem_u32(smem);
    const int tid  = threadIdx.x;
    const int wid  = tid >> 5;
    const int lane = tid & 31;
    const int bh = blockIdx.y;
    const int qb = (int)gridDim.x - 1 - (int)blockIdx.x;   // heavy tiles first
    const int q0 = qb * 128;
    const int g   = lane >> 2;
    const int tig = lane & 3;

    const int a_row = (lane & 7) | (((lane >> 3) & 1) << 3);
    const int a_kb  = (lane >> 4) * 16;
    const int b_row = (lane & 7) | ((lane >> 4) << 3);
    const int b_kb  = ((lane >> 3) & 1) * 16;
    const int vt_row = lane & 15;
    const int vt_cb  = (lane >> 4) * 16;

    const __nv_bfloat16* Qh = g_qh + (size_t)bh * TT * DD;
    const __nv_bfloat16* Ql = g_ql + (size_t)bh * TT * DD;
    const __nv_bfloat16* Kh = g_kh + (size_t)bh * TT * DD;
    const __nv_bfloat16* Kl = g_kl + (size_t)bh * TT * DD;
    const __nv_bfloat16* Vh = g_vh + (size_t)bh * TT * DD;
    const __nv_bfloat16* Vl = g_vl + (size_t)bh * TT * DD;

    const int cr = tid >> 3;
    const int cc = tid & 7;

    {
#pragma unroll
        for (int i = 0; i < 4; i++) {
            const int r = cr + i * 32;
            const uint32_t so = sw128((uint32_t)(r * 128 + cc * 16));
            const size_t off = (size_t)(q0 + r) * DD + cc * 8;
            cpasync16(sb + FQ_H + so, Qh + off);
            cpasync16(sb + FQ_L + so, Ql + off);
        }
    }

    auto issue_tile = [&](int t) {
        const int jt = t * 64;
        const uint32_t bb = sb + FKV + (uint32_t)(t & 1) * FA_BUF;
#pragma unroll
        for (int i = 0; i < 2; i++) {
            const int r = cr + i * 32;
            const uint32_t so = sw128((uint32_t)(r * 128 + cc * 16));
            const size_t off = (size_t)(jt + r) * DD + cc * 8;
            cpasync16(bb + FK_H + so, Kh + off);
            cpasync16(bb + FK_L + so, Kl + off);
            cpasync16(bb + FV_H + so, Vh + off);
            cpasync16(bb + FV_L + so, Vl + off);
        }
        CP_COMMIT();
    };

    issue_tile(0);

    const int NTL = qb * 2 + 2;
    const int wqmin = q0 + wid * 16;
    const int wqmax = wqmin + 15;
    const int r0 = wqmin + g;
    const int r1 = r0 + 8;

    float o[8][4] = {};
    float m0 = -1e30f, m1 = -1e30f, l0 = 0.0f, l1 = 0.0f;
    uint32_t qfh[4][4], qfl[4][4];

    for (int t = 0; t < NTL; t++) {
        if (t + 1 < NTL) {
            issue_tile(t + 1);
            CP_WAIT(1);
        } else {
            CP_WAIT(0);
        }
        __syncthreads();

        if (t == 0) {
#pragma unroll
            for (int k16 = 0; k16 < 4; k16++) {
                const uint32_t off =
                    sw128((uint32_t)((wid * 16 + a_row) * 128 + k16 * 32 + a_kb));
                ldsm4(qfh[k16], sb + FQ_H + off);
                ldsm4(qfl[k16], sb + FQ_L + off);
            }
        }

        const int jt = t * 64;
        if (jt <= wqmax) {
            const uint32_t bb = sb + FKV + (uint32_t)(t & 1) * FA_BUF;

            float s[8][4] = {};
#pragma unroll
            for (int g2 = 0; g2 < 4; g2++) {
#pragma unroll
                for (int k16 = 0; k16 < 4; k16++) {
                    const uint32_t off =
                        sw128((uint32_t)((g2 * 16 + b_row) * 128 + k16 * 32 + b_kb));
                    uint32_t rbh[4], rbl[4];
                    ldsm4(rbh, bb + FK_H + off);
                    ldsm4(rbl, bb + FK_L + off);
                    mma_bf16(s[g2*2],   qfh[k16], rbh);
                    mma_bf16(s[g2*2+1], qfh[k16], rbh + 2);
                    mma_bf16(s[g2*2],   qfh[k16], rbl);
                    mma_bf16(s[g2*2+1], qfh[k16], rbl + 2);
                    mma_bf16(s[g2*2],   qfl[k16], rbh);
                    mma_bf16(s[g2*2+1], qfl[k16], rbh + 2);
                }
            }

            if (jt + 63 > wqmin) {
#pragma unroll
                for (int st = 0; st < 8; st++) {
                    const int k = jt + st * 8 + tig * 2;
                    if (k     > r0) s[st][0] = -1e30f;
                    if (k + 1 > r0) s[st][1] = -1e30f;
                    if (k     > r1) s[st][2] = -1e30f;
                    if (k + 1 > r1) s[st][3] = -1e30f;
                }
            }

            float mx0 = -1e30f, mx1 = -1e30f;
#pragma unroll
            for (int st = 0; st < 8; st++) {
                mx0 = fmaxf(mx0, fmaxf(s[st][0], s[st][1]));
                mx1 = fmaxf(mx1, fmaxf(s[st][2], s[st][3]));
            }
            mx0 = fmaxf(mx0, __shfl_xor_sync(0xffffffffu, mx0, 1));
            mx0 = fmaxf(mx0, __shfl_xor_sync(0xffffffffu, mx0, 2));
            mx1 = fmaxf(mx1, __shfl_xor_sync(0xffffffffu, mx1, 1));
            mx1 = fmaxf(mx1, __shfl_xor_sync(0xffffffffu, mx1, 2));

            const float mt0 = fmaxf(m0, mx0);
            const float mt1 = fmaxf(m1, mx1);
            const float rs0 = __expf(m0 - mt0);
            const float rs1 = __expf(m1 - mt1);
            l0 *= rs0; l1 *= rs1;
            m0 = mt0;  m1 = mt1;
#pragma unroll
            for (int st = 0; st < 8; st++) {
                o[st][0] *= rs0; o[st][1] *= rs0;
                o[st][2] *= rs1; o[st][3] *= rs1;
            }

            float ps0 = 0.0f, ps1 = 0.0f;
#pragma unroll
            for (int st = 0; st < 8; st++) {
                s[st][0] = __expf(s[st][0] - m0);
                s[st][1] = __expf(s[st][1] - m0);
                s[st][2] = __expf(s[st][2] - m1);
                s[st][3] = __expf(s[st][3] - m1);
                ps0 += s[st][0] + s[st][1];
                ps1 += s[st][2] + s[st][3];
            }
            ps0 += __shfl_xor_sync(0xffffffffu, ps0, 1);
            ps0 += __shfl_xor_sync(0xffffffffu, ps0, 2);
            ps1 += __shfl_xor_sync(0xffffffffu, ps1, 1);
            ps1 += __shfl_xor_sync(0xffffffffu, ps1, 2);
            l0 += ps0; l1 += ps1;

#pragma unroll
            for (int k16 = 0; k16 < 4; k16++) {
                uint32_t ah[4], al[4];
                pack_split2(s[2*k16][0],   s[2*k16][1],   ah[0], al[0]);
                pack_split2(s[2*k16][2],   s[2*k16][3],   ah[1], al[1]);
                pack_split2(s[2*k16+1][0], s[2*k16+1][1], ah[2], al[2]);
                pack_split2(s[2*k16+1][2], s[2*k16+1][3], ah[3], al[3]);
#pragma unroll
                for (int g2 = 0; g2 < 4; g2++) {
                    const uint32_t off =
                        sw128((uint32_t)((k16 * 16 + vt_row) * 128 + g2 * 32 + vt_cb));
                    uint32_t vbh[4], vbl[4];
                    ldsm4t(vbh, bb + FV_H + off);
                    ldsm4t(vbl, bb + FV_L + off);
                    mma_bf16(o[g2*2],   ah, vbh);
                    mma_bf16(o[g2*2+1], ah, vbh + 2);
                    mma_bf16(o[g2*2],   ah, vbl);
                    mma_bf16(o[g2*2+1], ah, vbl + 2);
                    mma_bf16(o[g2*2],   al, vbh);
                    mma_bf16(o[g2*2+1], al, vbh + 2);
                }
            }
        }
        __syncthreads();
    }

    const int b = bh >> 4;
    const int h = bh & 15;
    const float inv0 = 1.0f / l0;
    const float inv1 = 1.0f / l1;
    const size_t row0 = ((size_t)(b * TT + r0)) * CC + h * DD;
    const size_t row1 = ((size_t)(b * TT + r1)) * CC + h * DD;
#pragma unroll
    for (int st = 0; st < 8; st++) {
        const int col = st * 8 + tig * 2;
        uint32_t hi0, lo0, hi1, lo1;
        pack_split2(o[st][0] * inv0, o[st][1] * inv0, hi0, lo0);
        pack_split2(o[st][2] * inv1, o[st][3] * inv1, hi1, lo1);
        *(uint32_t*)(g_ath + row0 + col) = hi0;
        *(uint32_t*)(g_atl + row0 + col) = lo0;
        *(uint32_t*)(g_ath + row1 + col) = hi1;
        *(uint32_t*)(g_atl + row1 + col) = lo1;
    }
}

// ---------------- launch ------------------------------------------------------
extern "C" void kernel_launch(void* const* d_in, const int* in_sizes, int n_in,
                              void* d_out, int out_size)
{
    const float* x    = (const float*)d_in[0];
    const float* Wqkv = (const float*)d_in[1];
    const float* Wo   = (const float*)d_in[2];
    const float* bo   = (const float*)d_in[3];
    float* out = (float*)d_out;

    (void)in_sizes; (void)n_in; (void)out_size;

    static int smem_set = 0;
    if (!smem_set) {
        cudaFuncSetAttribute(mm_bf16_kernel,
                             cudaFuncAttributeMaxDynamicSharedMemorySize, SM_TOTAL);
        cudaFuncSetAttribute(attn_mma_kernel,
                             cudaFuncAttributeMaxDynamicSharedMemorySize, FA_SMEM);
        smem_set = 1;
    }

    __nv_bfloat16 *xh, *xl, *wqh, *wql, *ath, *atl, *woh, *wol;
    cudaGetSymbolAddress((void**)&xh,  g_xh);
    cudaGetSymbolAddress((void**)&xl,  g_xl);
    cudaGetSymbolAddress((void**)&wqh, g_wqkvTh);
    cudaGetSymbolAddress((void**)&wql, g_wqkvTl);
    cudaGetSymbolAddress((void**)&ath, g_ath);
    cudaGetSymbolAddress((void**)&atl, g_atl);
    cudaGetSymbolAddress((void**)&woh, g_woTh);
    cudaGetSymbolAddress((void**)&wol, g_woTl);

    // 1) split x to bf16 hi/lo
    {
        int n4 = MTOT * CC / 4;
        split_kernel<<<(n4 + 255) / 256, 256>>>(x, xh, xl, n4);
    }
    // 2) transpose+split Wqkv -> [3072,1024]
    {
        dim3 grid(QKVN / 32, CC / 32);
        transpose_split_kernel<<<grid, dim3(32, 8)>>>(Wqkv, wqh, wql, CC, QKVN);
    }
    // 3) QKV GEMM with fused RoPE + split epilogue
    {
        dim3 grid(QKVN / 128, MTOT / 128);   // (24, 32)
        mm_bf16_kernel<<<grid, MM_THREADS, SM_TOTAL>>>(
            xh, xl, wqh, wql, nullptr, nullptr, QKVN, CC, 1);
    }
    // 4) causal flash attention on tensor cores
    {
        dim3 grid(TT / 128, BB * HH);
        attn_mma_kernel<<<grid, FA_THREADS, FA_SMEM>>>();
    }
    // 5) transpose+split Wo
    {
        dim3 grid(CC / 32, CC / 32);
        transpose_split_kernel<<<grid, dim3(32, 8)>>>(Wo, woh, wol, CC, CC);
    }
    // 6) output projection (HMMA) + bias
    {
        dim3 grid(CC / 128, MTOT / 128);     // (8, 32)
        mm_bf16_kernel<<<grid, MM_THREADS, SM_TOTAL>>>(
            ath, atl, woh, wol, bo, out, CC, CC, 0);
    }
}